// round 9
// baseline (speedup 1.0000x reference)
#include <cuda_runtime.h>
#include <cuda_bf16.h>
#include <cstdint>
#include <float.h>

#define NQ    8
#define BINS  1024
#define DIM   256
#define BB    16
#define TT    1500
#define NN    (BB * TT)
#define NPAD  24064
#define NTILE 188

// device scratch
__device__ float g_res[NPAD * DIM];          // residual, D-permuted within 8-groups
__device__ float g_acc[NPAD * DIM];          // natural D order
__device__ float g_cbp[NQ * BINS * DIM];     // permuted codebook copy
__device__ int   g_cand[NPAD * 64];
__device__ float g_cand_s[NPAD * 64];
__device__ float g_cbsq[NQ * BINS];
__device__ float g_partial[NQ * NN];

// D permutation within each 8-group
__device__ __forceinline__ int permD(int o) { return (o & ~7) | ((o & 3) << 1) | ((o & 4) >> 2); }
__device__ __forceinline__ int invD(int p)  { return (p & ~7) | ((p & 1) << 2) | ((p & 6) >> 1); }

// ---------------- helpers ----------------
__device__ __forceinline__ uint32_t smem_u32(const void* p) {
    uint32_t a;
    asm("{ .reg .u64 t; cvta.to.shared.u64 t, %1; cvt.u32.u64 %0, t; }" : "=r"(a) : "l"(p));
    return a;
}
__device__ __forceinline__ void cp_async16(uint32_t dst, const void* src) {
    asm volatile("cp.async.cg.shared.global [%0], [%1], 16;" :: "r"(dst), "l"(src) : "memory");
}
#define CP_COMMIT() asm volatile("cp.async.commit_group;" ::: "memory")
#define CP_WAIT1()  asm volatile("cp.async.wait_group 1;" ::: "memory")

__device__ __forceinline__ void mma_tf32(float* c, const uint32_t* a, const uint32_t* b) {
    asm volatile(
        "mma.sync.aligned.m16n8k8.row.col.f32.tf32.tf32.f32 "
        "{%0,%1,%2,%3}, {%4,%5,%6,%7}, {%8,%9}, {%0,%1,%2,%3};"
        : "+f"(c[0]), "+f"(c[1]), "+f"(c[2]), "+f"(c[3])
        : "r"(a[0]), "r"(a[1]), "r"(a[2]), "r"(a[3]), "r"(b[0]), "r"(b[1]));
}

// smem floats: A[3][128][32] @0 (12288), B[3][128][32] @12288 (12288), cbsq[512] @24576
#define SA_OFF(s)   ((s) * 4096)
#define SB_OFF(s)   (12288 + (s) * 4096)
#define SQ(i)       (24576 + (i))
#define SMEM_BYTES  (25088 * 4)

// ---------------- init: x (B,D,T) -> g_res (N, permD); z==16 slice zeroes pad ----------------
__global__ void rvq_init(const float* __restrict__ x) {
    __shared__ float s[32][33];
    if (blockIdx.z == 16) {
        int idx = (blockIdx.y * 47 + blockIdx.x) * 1024 + threadIdx.y * 32 + threadIdx.x;
        if (idx < (NPAD - NN) * DIM) g_res[(size_t)NN * DIM + idx] = 0.0f;
        return;
    }
    int b = blockIdx.z, d0 = blockIdx.y * 32, t0 = blockIdx.x * 32;
    int tx = threadIdx.x, ty = threadIdx.y;
    int t = t0 + tx;
    if (t < TT) s[ty][tx] = x[((size_t)b * DIM + d0 + ty) * TT + t];
    __syncthreads();
    int t2 = t0 + ty;
    if (t2 < TT)
        g_res[((size_t)(b * TT + t2)) * DIM + d0 + permD(tx)] = s[tx][ty];
}

// ---------------- cbsq + permuted codebook copy ----------------
__global__ void rvq_cbsq(const float* __restrict__ cb) {
    int warp = (blockIdx.x * blockDim.x + threadIdx.x) >> 5;
    int lane = threadIdx.x & 31;
    if (warp >= NQ * BINS) return;
    const float* row = cb + (size_t)warp * DIM;
    float s = 0.0f;
    for (int d = lane; d < DIM; d += 32) { float c = row[d]; s += c * c; }
    #pragma unroll
    for (int o = 16; o > 0; o >>= 1) s += __shfl_down_sync(0xffffffffu, s, o);
    if (lane == 0) g_cbsq[warp] = s;
}

__global__ void rvq_cbperm(const float* __restrict__ cbs) {
    size_t i = (size_t)blockIdx.x * blockDim.x + threadIdx.x;
    if (i >= (size_t)NQ * BINS * DIM) return;
    int d = (int)(i & 255);
    g_cbp[(i - d) + permD(d)] = cbs[i];
}

// ---------------- tf32 tensor-core argmax: 128 rows x 512 bins per CTA ----------------
// 512 threads, 16 warps (4m x 4n), warp tile 32x32, 32 accums/thread; top-2 per owner.
// chunks g = nt*8 + kc (nt 0..3 of 128 bins, kc 0..7 of K=32); 3-slot smem pipeline.
__global__ __launch_bounds__(512, 1) void rvq_argmax_tc(int q) {
    extern __shared__ float sm[];
    const uint32_t sb = smem_u32(sm);
    const int tid = threadIdx.x;
    const int lane = tid & 31, wid = tid >> 5;
    const int gid = lane >> 2, tg = lane & 3;
    const int wm = wid & 3, wn = wid >> 2;        // warp grid 4 (m) x 4 (n), warp tile 32x32
    const int mtile = blockIdx.x >> 1, half = blockIdx.x & 1;
    const int row0 = mtile * 128;
    const float* __restrict__ cbp = g_cbp + ((size_t)q * BINS + half * 512) * DIM;

    sm[SQ(tid)] = g_cbsq[q * BINS + half * 512 + tid];

    // prefetch mapping: 512 threads, each does rows ur, ur+64 for A and B, 16B unit useg
    const int ur = tid >> 3, useg = tid & 7;      // ur 0..63
    const float* aG = g_res + (size_t)(row0 + ur) * DIM + useg * 4;
    const float* bG = cbp + (size_t)ur * DIM + useg * 4;
    const uint32_t wOff = (uint32_t)(ur * 32 + ((useg ^ (ur & 7)) << 2)) * 4u;

#define PREF(pg_) do { \
    const int slot_ = (pg_) % 3; \
    const uint32_t dA_ = sb + (uint32_t)SA_OFF(slot_) * 4u + wOff; \
    const uint32_t dB_ = sb + (uint32_t)SB_OFF(slot_) * 4u + wOff; \
    const float* sA_ = aG + ((pg_) & 7) * 32; \
    const float* sB_ = bG + (size_t)((pg_) >> 3) * 32768 + ((pg_) & 7) * 32; \
    cp_async16(dA_,         sA_); \
    cp_async16(dA_ + 8192u, sA_ + 64 * DIM); \
    cp_async16(dB_,         sB_); \
    cp_async16(dB_ + 8192u, sB_ + 64 * DIM); \
    CP_COMMIT(); \
} while (0)

    float ts[4][2]; int ti[4][2];
    #pragma unroll
    for (int s = 0; s < 4; s++) {
        ts[s][0] = -FLT_MAX; ts[s][1] = -FLT_MAX;
        ti[s][0] = 0; ti[s][1] = 0;
    }

    float c[2][4][4];
    #pragma unroll
    for (int mi = 0; mi < 2; mi++)
        #pragma unroll
        for (int ni = 0; ni < 4; ni++)
            #pragma unroll
            for (int v = 0; v < 4; v++) c[mi][ni][v] = 0.0f;

#define FOLD(slot, sc, kg) do { \
    if ((sc) > ts[slot][0]) { \
        ts[slot][1] = ts[slot][0]; ti[slot][1] = ti[slot][0]; \
        ts[slot][0] = (sc); ti[slot][0] = (kg); \
    } else if ((sc) > ts[slot][1]) { ts[slot][1] = (sc); ti[slot][1] = (kg); } \
} while (0)

    PREF(0);
    PREF(1);

    #pragma unroll 1
    for (int g = 0; g < 32; g++) {
        CP_WAIT1();            // chunk g landed (g+1 still pending)
        __syncthreads();       // visibility; slot (g+2)%3 fully consumed (iter g-1)
        if (g + 2 < 32) { PREF(g + 2); } else { CP_COMMIT(); }

        const int buf = g % 3;
        const uint32_t aBase = (uint32_t)SA_OFF(buf);
        const uint32_t bBase = (uint32_t)SB_OFF(buf);
        #pragma unroll
        for (int kk = 0; kk < 4; kk++) {
            const int colp = (((2 * kk + (tg >> 1)) ^ gid) << 2) + 2 * (tg & 1);
            uint32_t a[2][4];
            #pragma unroll
            for (int mi = 0; mi < 2; mi++) {
                int r = wm * 32 + mi * 16 + gid;
                float2 av0 = *(const float2*)&sm[aBase + r * 32 + colp];
                float2 av1 = *(const float2*)&sm[aBase + (r + 8) * 32 + colp];
                a[mi][0] = __float_as_uint(av0.x);
                a[mi][1] = __float_as_uint(av1.x);
                a[mi][2] = __float_as_uint(av0.y);
                a[mi][3] = __float_as_uint(av1.y);
            }
            #pragma unroll
            for (int ni = 0; ni < 4; ni++) {
                int n = wn * 32 + ni * 8 + gid;
                float2 bv = *(const float2*)&sm[bBase + n * 32 + colp];
                uint32_t b[2] = { __float_as_uint(bv.x), __float_as_uint(bv.y) };
                mma_tf32(c[0][ni], a[0], b);
                mma_tf32(c[1][ni], a[1], b);
            }
        }

        if ((g & 7) == 7) {
            const int nt = g >> 3;
            #pragma unroll
            for (int mi = 0; mi < 2; mi++)
                #pragma unroll
                for (int ni = 0; ni < 4; ni++) {
                    int cc = wn * 32 + ni * 8 + tg * 2;
                    int kl = nt * 128 + cc;
                    int kg = half * 512 + kl;
                    float q0 = sm[SQ(kl)], q1 = sm[SQ(kl + 1)];
                    float s0 = 2.0f * c[mi][ni][0] - q0;
                    float s1 = 2.0f * c[mi][ni][1] - q1;
                    float s2 = 2.0f * c[mi][ni][2] - q0;
                    float s3 = 2.0f * c[mi][ni][3] - q1;
                    FOLD(mi * 2 + 0, s0, kg);
                    FOLD(mi * 2 + 0, s1, kg + 1);
                    FOLD(mi * 2 + 1, s2, kg);
                    FOLD(mi * 2 + 1, s3, kg + 1);
                    #pragma unroll
                    for (int v = 0; v < 4; v++) c[mi][ni][v] = 0.0f;
                }
        }
    }

    // write 2 candidates per owned (row, owner); owner = wn*4+tg (16 owners)
    const int owner = wn * 4 + tg;
    #pragma unroll
    for (int s = 0; s < 4; s++) {
        int row = row0 + wm * 32 + (s >> 1) * 16 + (s & 1) * 8 + gid;
        size_t base = (size_t)row * 64 + half * 32 + owner * 2;
        g_cand[base]     = ti[s][0];  g_cand_s[base]     = ts[s][0];
        g_cand[base + 1] = ti[s][1];  g_cand_s[base + 1] = ts[s][1];
    }
}

// ---------------- exact select (fp64, margin-filtered) + update ----------------
__global__ void rvq_select_update(const float* __restrict__ cbs,
                                  float* __restrict__ codes_out, int q) {
    __shared__ float sApprox[64];
    __shared__ double sS[64];
    __shared__ int sK;
    __shared__ float red[8];
    __shared__ float sMax;
    const int n = blockIdx.x, tid = threadIdx.x;
    const int w = tid >> 5, lane = tid & 31;
    const float* __restrict__ cb = cbs + (size_t)q * BINS * DIM;

    if (tid < 64) {
        sApprox[tid] = g_cand_s[(size_t)n * 64 + tid];
        sS[tid] = -1e300;
    }
    __syncthreads();
    if (tid < 32) {
        float a = fmaxf(sApprox[tid], sApprox[tid + 32]);
        #pragma unroll
        for (int o = 16; o > 0; o >>= 1) a = fmaxf(a, __shfl_down_sync(0xffffffffu, a, o));
        if (tid == 0) sMax = a;
    }
    __syncthreads();

    const float thr = sMax - 0.3f;
    #pragma unroll 1
    for (int c8 = 0; c8 < 8; c8++) {
        const int ci = w * 8 + c8;
        if (sApprox[ci] >= thr) {
            const int cand = g_cand[(size_t)n * 64 + ci];
            const float* r = g_res + (size_t)n * DIM;
            const float* c = cb + (size_t)cand * DIM;
            double dot = 0.0, sq = 0.0;
            #pragma unroll
            for (int d = lane; d < DIM; d += 32) {
                double rv = r[d], cv = c[invD(d)];
                dot += rv * cv; sq += cv * cv;
            }
            #pragma unroll
            for (int o = 16; o > 0; o >>= 1) {
                dot += __shfl_down_sync(0xffffffffu, dot, o);
                sq  += __shfl_down_sync(0xffffffffu, sq, o);
            }
            if (lane == 0) sS[ci] = 2.0 * dot - sq;
        }
    }
    __syncthreads();
    if (tid == 0) {
        double best = -1e301; int bk = 1 << 30;
        #pragma unroll
        for (int j = 0; j < 64; j++) {
            double s = sS[j];
            int k = g_cand[(size_t)n * 64 + j];
            if (s > best || (s == best && k < bk)) { best = s; bk = k; }
        }
        sK = bk;
    }
    __syncthreads();

    const int k = sK;
    const int od = invD(tid);
    const float qv = cb[(size_t)k * DIM + od];
    const size_t off = (size_t)n * DIM + tid;
    const float rn = g_res[off] - qv;
    g_res[off] = rn;
    if (q == 0) g_acc[(size_t)n * DIM + od] = qv;
    else        g_acc[(size_t)n * DIM + od] += qv;

    float sq2 = rn * rn;
    #pragma unroll
    for (int o = 16; o > 0; o >>= 1) sq2 += __shfl_down_sync(0xffffffffu, sq2, o);
    if (lane == 0) red[w] = sq2;
    __syncthreads();
    if (tid == 0) {
        float tot = 0.0f;
        #pragma unroll
        for (int ww = 0; ww < 8; ww++) tot += red[ww];
        g_partial[q * NN + n] = tot;
        codes_out[q * NN + n] = (float)k;
    }
}

// ---------------- finalize: g_acc (N,D natural) -> out (B,D,T) ----------------
__global__ void rvq_finalize(float* __restrict__ out) {
    __shared__ float s[32][33];
    int b = blockIdx.z, d0 = blockIdx.y * 32, t0 = blockIdx.x * 32;
    int tx = threadIdx.x, ty = threadIdx.y;
    int t = t0 + ty;
    if (t < TT) s[ty][tx] = g_acc[((size_t)(b * TT + t)) * DIM + d0 + tx];
    __syncthreads();
    int t2 = t0 + tx;
    if (t2 < TT) out[((size_t)b * DIM + d0 + ty) * TT + t2] = s[tx][ty];
}

// ---------------- penalty ----------------
__global__ void rvq_penalty(float* __restrict__ out) {
    __shared__ float red[8];
    const int tid = threadIdx.x;
    float s = 0.0f;
    for (int i = tid; i < NQ * NN; i += 256) s += g_partial[i];
    #pragma unroll
    for (int o = 16; o > 0; o >>= 1) s += __shfl_down_sync(0xffffffffu, s, o);
    if ((tid & 31) == 0) red[tid >> 5] = s;
    __syncthreads();
    if (tid == 0) {
        float tot = 0.0f;
        #pragma unroll
        for (int w = 0; w < 8; w++) tot += red[w];
        out[(size_t)BB * DIM * TT + (size_t)NQ * NN] =
            tot / ((float)NQ * (float)NN * (float)DIM);
    }
}

// ---------------- launch ----------------
extern "C" void kernel_launch(void* const* d_in, const int* in_sizes, int n_in,
                              void* d_out, int out_size) {
    const float* x   = (const float*)d_in[0];
    const float* cbs = (const float*)d_in[1];
    float* out = (float*)d_out;
    float* codes_out = out + (size_t)BB * DIM * TT;

    cudaFuncSetAttribute(rvq_argmax_tc,
                         cudaFuncAttributeMaxDynamicSharedMemorySize, SMEM_BYTES);

    dim3 tb(32, 32);
    rvq_init<<<dim3(47, 8, 17), tb>>>(x);
    rvq_cbsq<<<1024, 256>>>(cbs);
    rvq_cbperm<<<(NQ * BINS * DIM + 255) / 256, 256>>>(cbs);

    for (int q = 0; q < NQ; q++) {
        rvq_argmax_tc<<<NTILE * 2, 512, SMEM_BYTES>>>(q);
        rvq_select_update<<<NN, 256>>>(cbs, codes_out, q);
    }

    rvq_finalize<<<dim3(47, 8, 16), tb>>>(out);
    rvq_penalty<<<1, 256>>>(out);
}

// round 10
// speedup vs baseline: 1.1208x; 1.1208x over previous
#include <cuda_runtime.h>
#include <cuda_bf16.h>
#include <cstdint>
#include <float.h>

#define NQ    8
#define BINS  1024
#define DIM   256
#define BB    16
#define TT    1500
#define NN    (BB * TT)
#define NPAD  24064
#define NTILE 188

// device scratch
__device__ float g_res[NPAD * DIM];          // residual, D-permuted within 8-groups
__device__ float g_acc[NPAD * DIM];          // natural D order
__device__ float g_cbp[NQ * BINS * DIM];     // permuted codebook copy
__device__ int   g_cand[NPAD * 64];
__device__ float g_cand_s[NPAD * 64];
__device__ float g_cbsq[NQ * BINS];
__device__ float g_partial[NQ * NN];

// D permutation within each 8-group
__device__ __forceinline__ int permD(int o) { return (o & ~7) | ((o & 3) << 1) | ((o & 4) >> 2); }
__device__ __forceinline__ int invD(int p)  { return (p & ~7) | ((p & 1) << 2) | ((p & 6) >> 1); }

// ---------------- helpers ----------------
__device__ __forceinline__ uint32_t smem_u32(const void* p) {
    uint32_t a;
    asm("{ .reg .u64 t; cvta.to.shared.u64 t, %1; cvt.u32.u64 %0, t; }" : "=r"(a) : "l"(p));
    return a;
}
__device__ __forceinline__ void cp_async16(uint32_t dst, const void* src) {
    asm volatile("cp.async.cg.shared.global [%0], [%1], 16;" :: "r"(dst), "l"(src) : "memory");
}
#define CP_COMMIT() asm volatile("cp.async.commit_group;" ::: "memory")
#define CP_WAIT1()  asm volatile("cp.async.wait_group 1;" ::: "memory")

__device__ __forceinline__ void mma_tf32(float* c, const uint32_t* a, const uint32_t* b) {
    asm volatile(
        "mma.sync.aligned.m16n8k8.row.col.f32.tf32.tf32.f32 "
        "{%0,%1,%2,%3}, {%4,%5,%6,%7}, {%8,%9}, {%0,%1,%2,%3};"
        : "+f"(c[0]), "+f"(c[1]), "+f"(c[2]), "+f"(c[3])
        : "r"(a[0]), "r"(a[1]), "r"(a[2]), "r"(a[3]), "r"(b[0]), "r"(b[1]));
}

// smem floats: A[3][128][32] @0 (12288), B[3][128][32] @12288 (12288), cbsq[512] @24576
#define SA_OFF(s)   ((s) * 4096)
#define SB_OFF(s)   (12288 + (s) * 4096)
#define SQ(i)       (24576 + (i))
#define SMEM_BYTES  (25088 * 4)

// ---------------- init: x (B,D,T) -> g_res (N, permD); z==16 slice zeroes pad ----------------
__global__ void rvq_init(const float* __restrict__ x) {
    __shared__ float s[32][33];
    if (blockIdx.z == 16) {
        int idx = (blockIdx.y * 47 + blockIdx.x) * 1024 + threadIdx.y * 32 + threadIdx.x;
        if (idx < (NPAD - NN) * DIM) g_res[(size_t)NN * DIM + idx] = 0.0f;
        return;
    }
    int b = blockIdx.z, d0 = blockIdx.y * 32, t0 = blockIdx.x * 32;
    int tx = threadIdx.x, ty = threadIdx.y;
    int t = t0 + tx;
    if (t < TT) s[ty][tx] = x[((size_t)b * DIM + d0 + ty) * TT + t];
    __syncthreads();
    int t2 = t0 + ty;
    if (t2 < TT)
        g_res[((size_t)(b * TT + t2)) * DIM + d0 + permD(tx)] = s[tx][ty];
}

// ---------------- cbsq + permuted codebook copy ----------------
__global__ void rvq_cbsq(const float* __restrict__ cb) {
    int warp = (blockIdx.x * blockDim.x + threadIdx.x) >> 5;
    int lane = threadIdx.x & 31;
    if (warp >= NQ * BINS) return;
    const float* row = cb + (size_t)warp * DIM;
    float s = 0.0f;
    for (int d = lane; d < DIM; d += 32) { float c = row[d]; s += c * c; }
    #pragma unroll
    for (int o = 16; o > 0; o >>= 1) s += __shfl_down_sync(0xffffffffu, s, o);
    if (lane == 0) g_cbsq[warp] = s;
}

__global__ void rvq_cbperm(const float* __restrict__ cbs) {
    size_t i = (size_t)blockIdx.x * blockDim.x + threadIdx.x;
    if (i >= (size_t)NQ * BINS * DIM) return;
    int d = (int)(i & 255);
    g_cbp[(i - d) + permD(d)] = cbs[i];
}

// ---------------- tf32 tensor-core argmax: 128 rows x 512 bins per CTA ----------------
// 512 threads, 16 warps (4m x 4n), warp tile 32x32, 32 accums/thread; top-2 per owner.
// Bank-conflict-free swizzle: group c of row r stored at physical group c ^ ((r&3)<<1).
__global__ __launch_bounds__(512, 1) void rvq_argmax_tc(int q) {
    extern __shared__ float sm[];
    const uint32_t sb = smem_u32(sm);
    const int tid = threadIdx.x;
    const int lane = tid & 31, wid = tid >> 5;
    const int gid = lane >> 2, tg = lane & 3;
    const int wm = wid & 3, wn = wid >> 2;        // warp grid 4 (m) x 4 (n), warp tile 32x32
    const int mtile = blockIdx.x >> 1, half = blockIdx.x & 1;
    const int row0 = mtile * 128;
    const float* __restrict__ cbp = g_cbp + ((size_t)q * BINS + half * 512) * DIM;

    sm[SQ(tid)] = g_cbsq[q * BINS + half * 512 + tid];

    // prefetch mapping: 512 threads, each does rows ur, ur+64 for A and B, 16B unit useg
    const int ur = tid >> 3, useg = tid & 7;      // ur 0..63
    const float* aG = g_res + (size_t)(row0 + ur) * DIM + useg * 4;
    const float* bG = cbp + (size_t)ur * DIM + useg * 4;
    // physical group = useg ^ ((ur&3)<<1); rows +64 share ur&3 -> same offset
    const uint32_t wOff = (uint32_t)(ur * 32 + ((useg ^ ((ur & 3) << 1)) << 2)) * 4u;

#define PREF(pg_) do { \
    const int slot_ = (pg_) % 3; \
    const uint32_t dA_ = sb + (uint32_t)SA_OFF(slot_) * 4u + wOff; \
    const uint32_t dB_ = sb + (uint32_t)SB_OFF(slot_) * 4u + wOff; \
    const float* sA_ = aG + ((pg_) & 7) * 32; \
    const float* sB_ = bG + (size_t)((pg_) >> 3) * 32768 + ((pg_) & 7) * 32; \
    cp_async16(dA_,         sA_); \
    cp_async16(dA_ + 8192u, sA_ + 64 * DIM); \
    cp_async16(dB_,         sB_); \
    cp_async16(dB_ + 8192u, sB_ + 64 * DIM); \
    CP_COMMIT(); \
} while (0)

    float ts[4][2]; int ti[4][2];
    #pragma unroll
    for (int s = 0; s < 4; s++) {
        ts[s][0] = -FLT_MAX; ts[s][1] = -FLT_MAX;
        ti[s][0] = 0; ti[s][1] = 0;
    }

    float c[2][4][4];
    #pragma unroll
    for (int mi = 0; mi < 2; mi++)
        #pragma unroll
        for (int ni = 0; ni < 4; ni++)
            #pragma unroll
            for (int v = 0; v < 4; v++) c[mi][ni][v] = 0.0f;

#define FOLD(slot, sc, kg) do { \
    if ((sc) > ts[slot][0]) { \
        ts[slot][1] = ts[slot][0]; ti[slot][1] = ti[slot][0]; \
        ts[slot][0] = (sc); ti[slot][0] = (kg); \
    } else if ((sc) > ts[slot][1]) { ts[slot][1] = (sc); ti[slot][1] = (kg); } \
} while (0)

    PREF(0);
    PREF(1);

    #pragma unroll 1
    for (int g = 0; g < 32; g++) {
        CP_WAIT1();            // chunk g landed (g+1 still pending)
        __syncthreads();       // visibility; slot (g+2)%3 fully consumed (iter g-1)
        if (g + 2 < 32) { PREF(g + 2); } else { CP_COMMIT(); }

        const int buf = g % 3;
        const uint32_t aBase = (uint32_t)SA_OFF(buf);
        const uint32_t bBase = (uint32_t)SB_OFF(buf);
        #pragma unroll
        for (int kk = 0; kk < 4; kk++) {
            // logical group c = 2kk + (tg>>1); physical = c ^ ((row&3)<<1), row&3 = gid&3
            const int colp = (((2 * kk + (tg >> 1)) ^ ((gid & 3) << 1)) << 2) + 2 * (tg & 1);
            uint32_t a[2][4];
            #pragma unroll
            for (int mi = 0; mi < 2; mi++) {
                int r = wm * 32 + mi * 16 + gid;
                float2 av0 = *(const float2*)&sm[aBase + r * 32 + colp];
                float2 av1 = *(const float2*)&sm[aBase + (r + 8) * 32 + colp];
                a[mi][0] = __float_as_uint(av0.x);
                a[mi][1] = __float_as_uint(av1.x);
                a[mi][2] = __float_as_uint(av0.y);
                a[mi][3] = __float_as_uint(av1.y);
            }
            #pragma unroll
            for (int ni = 0; ni < 4; ni++) {
                int n = wn * 32 + ni * 8 + gid;
                float2 bv = *(const float2*)&sm[bBase + n * 32 + colp];
                uint32_t b[2] = { __float_as_uint(bv.x), __float_as_uint(bv.y) };
                mma_tf32(c[0][ni], a[0], b);
                mma_tf32(c[1][ni], a[1], b);
            }
        }

        if ((g & 7) == 7) {
            const int nt = g >> 3;
            #pragma unroll
            for (int mi = 0; mi < 2; mi++)
                #pragma unroll
                for (int ni = 0; ni < 4; ni++) {
                    int cc = wn * 32 + ni * 8 + tg * 2;
                    int kl = nt * 128 + cc;
                    int kg = half * 512 + kl;
                    float q0 = sm[SQ(kl)], q1 = sm[SQ(kl + 1)];
                    float s0 = 2.0f * c[mi][ni][0] - q0;
                    float s1 = 2.0f * c[mi][ni][1] - q1;
                    float s2 = 2.0f * c[mi][ni][2] - q0;
                    float s3 = 2.0f * c[mi][ni][3] - q1;
                    FOLD(mi * 2 + 0, s0, kg);
                    FOLD(mi * 2 + 0, s1, kg + 1);
                    FOLD(mi * 2 + 1, s2, kg);
                    FOLD(mi * 2 + 1, s3, kg + 1);
                    #pragma unroll
                    for (int v = 0; v < 4; v++) c[mi][ni][v] = 0.0f;
                }
        }
    }

    // write 2 candidates per owned (row, owner); owner = wn*4+tg (16 owners)
    const int owner = wn * 4 + tg;
    #pragma unroll
    for (int s = 0; s < 4; s++) {
        int row = row0 + wm * 32 + (s >> 1) * 16 + (s & 1) * 8 + gid;
        size_t base = (size_t)row * 64 + half * 32 + owner * 2;
        g_cand[base]     = ti[s][0];  g_cand_s[base]     = ts[s][0];
        g_cand[base + 1] = ti[s][1];  g_cand_s[base + 1] = ts[s][1];
    }
}

// ---------------- exact select (fp64, margin-filtered) + update ----------------
__global__ void rvq_select_update(const float* __restrict__ cbs,
                                  float* __restrict__ codes_out, int q) {
    __shared__ float sApprox[64];
    __shared__ double sS[64];
    __shared__ int sK;
    __shared__ float red[8];
    __shared__ float sMax;
    const int n = blockIdx.x, tid = threadIdx.x;
    const int w = tid >> 5, lane = tid & 31;
    const float* __restrict__ cb = cbs + (size_t)q * BINS * DIM;

    if (tid < 64) {
        sApprox[tid] = g_cand_s[(size_t)n * 64 + tid];
        sS[tid] = -1e300;
    }
    __syncthreads();
    if (tid < 32) {
        float a = fmaxf(sApprox[tid], sApprox[tid + 32]);
        #pragma unroll
        for (int o = 16; o > 0; o >>= 1) a = fmaxf(a, __shfl_down_sync(0xffffffffu, a, o));
        if (tid == 0) sMax = a;
    }
    __syncthreads();

    const float thr = sMax - 0.3f;
    #pragma unroll 1
    for (int c8 = 0; c8 < 8; c8++) {
        const int ci = w * 8 + c8;
        if (sApprox[ci] >= thr) {
            const int cand = g_cand[(size_t)n * 64 + ci];
            const float* r = g_res + (size_t)n * DIM;
            const float* c = cb + (size_t)cand * DIM;
            double dot = 0.0, sq = 0.0;
            #pragma unroll
            for (int d = lane; d < DIM; d += 32) {
                double rv = r[d], cv = c[invD(d)];
                dot += rv * cv; sq += cv * cv;
            }
            #pragma unroll
            for (int o = 16; o > 0; o >>= 1) {
                dot += __shfl_down_sync(0xffffffffu, dot, o);
                sq  += __shfl_down_sync(0xffffffffu, sq, o);
            }
            if (lane == 0) sS[ci] = 2.0 * dot - sq;
        }
    }
    __syncthreads();
    if (tid == 0) {
        double best = -1e301; int bk = 1 << 30;
        #pragma unroll
        for (int j = 0; j < 64; j++) {
            double s = sS[j];
            int k = g_cand[(size_t)n * 64 + j];
            if (s > best || (s == best && k < bk)) { best = s; bk = k; }
        }
        sK = bk;
    }
    __syncthreads();

    const int k = sK;
    const int od = invD(tid);
    const float qv = cb[(size_t)k * DIM + od];
    const size_t off = (size_t)n * DIM + tid;
    const float rn = g_res[off] - qv;
    g_res[off] = rn;
    if (q == 0) g_acc[(size_t)n * DIM + od] = qv;
    else        g_acc[(size_t)n * DIM + od] += qv;

    float sq2 = rn * rn;
    #pragma unroll
    for (int o = 16; o > 0; o >>= 1) sq2 += __shfl_down_sync(0xffffffffu, sq2, o);
    if (lane == 0) red[w] = sq2;
    __syncthreads();
    if (tid == 0) {
        float tot = 0.0f;
        #pragma unroll
        for (int ww = 0; ww < 8; ww++) tot += red[ww];
        g_partial[q * NN + n] = tot;
        codes_out[q * NN + n] = (float)k;
    }
}

// ---------------- finalize: g_acc (N,D natural) -> out (B,D,T) ----------------
__global__ void rvq_finalize(float* __restrict__ out) {
    __shared__ float s[32][33];
    int b = blockIdx.z, d0 = blockIdx.y * 32, t0 = blockIdx.x * 32;
    int tx = threadIdx.x, ty = threadIdx.y;
    int t = t0 + ty;
    if (t < TT) s[ty][tx] = g_acc[((size_t)(b * TT + t)) * DIM + d0 + tx];
    __syncthreads();
    int t2 = t0 + tx;
    if (t2 < TT) out[((size_t)b * DIM + d0 + ty) * TT + t2] = s[tx][ty];
}

// ---------------- penalty ----------------
__global__ void rvq_penalty(float* __restrict__ out) {
    __shared__ float red[8];
    const int tid = threadIdx.x;
    float s = 0.0f;
    for (int i = tid; i < NQ * NN; i += 256) s += g_partial[i];
    #pragma unroll
    for (int o = 16; o > 0; o >>= 1) s += __shfl_down_sync(0xffffffffu, s, o);
    if ((tid & 31) == 0) red[tid >> 5] = s;
    __syncthreads();
    if (tid == 0) {
        float tot = 0.0f;
        #pragma unroll
        for (int w = 0; w < 8; w++) tot += red[w];
        out[(size_t)BB * DIM * TT + (size_t)NQ * NN] =
            tot / ((float)NQ * (float)NN * (float)DIM);
    }
}

// ---------------- launch ----------------
extern "C" void kernel_launch(void* const* d_in, const int* in_sizes, int n_in,
                              void* d_out, int out_size) {
    const float* x   = (const float*)d_in[0];
    const float* cbs = (const float*)d_in[1];
    float* out = (float*)d_out;
    float* codes_out = out + (size_t)BB * DIM * TT;

    cudaFuncSetAttribute(rvq_argmax_tc,
                         cudaFuncAttributeMaxDynamicSharedMemorySize, SMEM_BYTES);

    dim3 tb(32, 32);
    rvq_init<<<dim3(47, 8, 17), tb>>>(x);
    rvq_cbsq<<<1024, 256>>>(cbs);
    rvq_cbperm<<<(NQ * BINS * DIM + 255) / 256, 256>>>(cbs);

    for (int q = 0; q < NQ; q++) {
        rvq_argmax_tc<<<NTILE * 2, 512, SMEM_BYTES>>>(q);
        rvq_select_update<<<NN, 256>>>(cbs, codes_out, q);
    }

    rvq_finalize<<<dim3(47, 8, 16), tb>>>(out);
    rvq_penalty<<<1, 256>>>(out);
}

// round 12
// speedup vs baseline: 1.1779x; 1.0510x over previous
#include <cuda_runtime.h>
#include <cuda_bf16.h>
#include <cstdint>
#include <float.h>

#define NQ    8
#define BINS  1024
#define DIM   256
#define BB    16
#define TT    1500
#define NN    (BB * TT)
#define NPAD  24064
#define NTILE 188

// device scratch
__device__ float g_res[NPAD * DIM];          // residual, D-permuted within 8-groups
__device__ float g_acc[NPAD * DIM];          // natural D order
__device__ float g_cbp[NQ * BINS * DIM];     // permuted codebook copy
__device__ int   g_cand[NPAD * 64];
__device__ float g_cand_s[NPAD * 64];
__device__ float g_cbsq[NQ * BINS];
__device__ float g_partial[NQ * NN];

// D permutation within each 8-group
__device__ __forceinline__ int permD(int o) { return (o & ~7) | ((o & 3) << 1) | ((o & 4) >> 2); }
__device__ __forceinline__ int invD(int p)  { return (p & ~7) | ((p & 1) << 2) | ((p & 6) >> 1); }

// ---------------- helpers ----------------
__device__ __forceinline__ uint32_t smem_u32(const void* p) {
    uint32_t a;
    asm("{ .reg .u64 t; cvta.to.shared.u64 t, %1; cvt.u32.u64 %0, t; }" : "=r"(a) : "l"(p));
    return a;
}
__device__ __forceinline__ void cp_async16(uint32_t dst, const void* src) {
    asm volatile("cp.async.cg.shared.global [%0], [%1], 16;" :: "r"(dst), "l"(src) : "memory");
}
#define CP_COMMIT() asm volatile("cp.async.commit_group;" ::: "memory")
#define CP_WAIT1()  asm volatile("cp.async.wait_group 1;" ::: "memory")

__device__ __forceinline__ void mma_tf32(float* c, const uint32_t* a, const uint32_t* b) {
    asm volatile(
        "mma.sync.aligned.m16n8k8.row.col.f32.tf32.tf32.f32 "
        "{%0,%1,%2,%3}, {%4,%5,%6,%7}, {%8,%9}, {%0,%1,%2,%3};"
        : "+f"(c[0]), "+f"(c[1]), "+f"(c[2]), "+f"(c[3])
        : "r"(a[0]), "r"(a[1]), "r"(a[2]), "r"(a[3]), "r"(b[0]), "r"(b[1]));
}

// smem floats: A[3][128][32] @0 (12288), B[3][256][32] @12288 (24576), cbsq[512] @36864
#define SA_OFF(s)   ((s) * 4096)
#define SB_OFF(s)   (12288 + (s) * 8192)
#define SQ(i)       (36864 + (i))
#define SMEM_BYTES  (37376 * 4)

// ---------------- init: x (B,D,T) -> g_res (N, permD); z==16 slice zeroes pad ----------------
__global__ void rvq_init(const float* __restrict__ x) {
    __shared__ float s[32][33];
    if (blockIdx.z == 16) {
        int idx = (blockIdx.y * 47 + blockIdx.x) * 1024 + threadIdx.y * 32 + threadIdx.x;
        if (idx < (NPAD - NN) * DIM) g_res[(size_t)NN * DIM + idx] = 0.0f;
        return;
    }
    int b = blockIdx.z, d0 = blockIdx.y * 32, t0 = blockIdx.x * 32;
    int tx = threadIdx.x, ty = threadIdx.y;
    int t = t0 + tx;
    if (t < TT) s[ty][tx] = x[((size_t)b * DIM + d0 + ty) * TT + t];
    __syncthreads();
    int t2 = t0 + ty;
    if (t2 < TT)
        g_res[((size_t)(b * TT + t2)) * DIM + d0 + permD(tx)] = s[tx][ty];
}

// ---------------- cbsq + permuted codebook copy ----------------
__global__ void rvq_cbsq(const float* __restrict__ cb) {
    int warp = (blockIdx.x * blockDim.x + threadIdx.x) >> 5;
    int lane = threadIdx.x & 31;
    if (warp >= NQ * BINS) return;
    const float* row = cb + (size_t)warp * DIM;
    float s = 0.0f;
    for (int d = lane; d < DIM; d += 32) { float c = row[d]; s += c * c; }
    #pragma unroll
    for (int o = 16; o > 0; o >>= 1) s += __shfl_down_sync(0xffffffffu, s, o);
    if (lane == 0) g_cbsq[warp] = s;
}

__global__ void rvq_cbperm(const float* __restrict__ cbs) {
    size_t i = (size_t)blockIdx.x * blockDim.x + threadIdx.x;
    if (i >= (size_t)NQ * BINS * DIM) return;
    int d = (int)(i & 255);
    g_cbp[(i - d) + permD(d)] = cbs[i];
}

// ---------------- tf32 tensor-core argmax: 128 rows x 512 bins per CTA ----------------
// 512 threads, 16 warps (4m x 4n), warp tile 32x64, 64 accums/thread; top-2 per owner.
// chunk g = nt*8 + kc, nt in {0,1} covers 256 bins; 3-slot smem pipeline.
// Bank-conflict-free swizzle: group c of row r stored at physical group c ^ ((r&3)<<1).
__global__ __launch_bounds__(512, 1) void rvq_argmax_tc(int q) {
    extern __shared__ float sm[];
    const uint32_t sb = smem_u32(sm);
    const int tid = threadIdx.x;
    const int lane = tid & 31, wid = tid >> 5;
    const int gid = lane >> 2, tg = lane & 3;
    const int wm = wid & 3, wn = wid >> 2;        // warp grid 4 (m) x 4 (n), warp tile 32x64
    const int mtile = blockIdx.x >> 1, half = blockIdx.x & 1;
    const int row0 = mtile * 128;
    const float* __restrict__ cbp = g_cbp + ((size_t)q * BINS + half * 512) * DIM;

    sm[SQ(tid)] = g_cbsq[q * BINS + half * 512 + tid];

    // prefetch mapping: A rows ur, ur+64; B rows ur, ur+64, ur+128, ur+192
    const int ur = tid >> 3, useg = tid & 7;      // ur 0..63
    const float* aG = g_res + (size_t)(row0 + ur) * DIM + useg * 4;
    const float* bG = cbp + (size_t)ur * DIM + useg * 4;
    // physical group = useg ^ ((ur&3)<<1); rows +64k share ur&3 -> same offset
    const uint32_t wOff = (uint32_t)(ur * 32 + ((useg ^ ((ur & 3) << 1)) << 2)) * 4u;

#define PREF(pg_) do { \
    const int slot_ = (pg_) % 3; \
    const uint32_t dA_ = sb + (uint32_t)SA_OFF(slot_) * 4u + wOff; \
    const uint32_t dB_ = sb + (uint32_t)SB_OFF(slot_) * 4u + wOff; \
    const float* sA_ = aG + ((pg_) & 7) * 32; \
    const float* sB_ = bG + (size_t)((pg_) >> 3) * (256 * DIM) + ((pg_) & 7) * 32; \
    cp_async16(dA_,          sA_); \
    cp_async16(dA_ + 8192u,  sA_ + 64 * DIM); \
    cp_async16(dB_,          sB_); \
    cp_async16(dB_ + 8192u,  sB_ + 64 * DIM); \
    cp_async16(dB_ + 16384u, sB_ + 128 * DIM); \
    cp_async16(dB_ + 24576u, sB_ + 192 * DIM); \
    CP_COMMIT(); \
} while (0)

    float ts[4][2]; int ti[4][2];
    #pragma unroll
    for (int s = 0; s < 4; s++) {
        ts[s][0] = -FLT_MAX; ts[s][1] = -FLT_MAX;
        ti[s][0] = 0; ti[s][1] = 0;
    }

    float c[2][8][4];
    #pragma unroll
    for (int mi = 0; mi < 2; mi++)
        #pragma unroll
        for (int ni = 0; ni < 8; ni++)
            #pragma unroll
            for (int v = 0; v < 4; v++) c[mi][ni][v] = 0.0f;

#define FOLD(slot, sc, kg) do { \
    if ((sc) > ts[slot][0]) { \
        ts[slot][1] = ts[slot][0]; ti[slot][1] = ti[slot][0]; \
        ts[slot][0] = (sc); ti[slot][0] = (kg); \
    } else if ((sc) > ts[slot][1]) { ts[slot][1] = (sc); ti[slot][1] = (kg); } \
} while (0)

    PREF(0);
    PREF(1);

    #pragma unroll 1
    for (int g = 0; g < 16; g++) {
        CP_WAIT1();            // chunk g landed (g+1 still pending)
        __syncthreads();       // visibility; slot (g+2)%3 fully consumed (iter g-1)
        if (g + 2 < 16) { PREF(g + 2); } else { CP_COMMIT(); }

        const int buf = g % 3;
        const uint32_t aBase = (uint32_t)SA_OFF(buf);
        const uint32_t bBase = (uint32_t)SB_OFF(buf);
        #pragma unroll
        for (int kk = 0; kk < 4; kk++) {
            // logical group c = 2kk + (tg>>1); physical = c ^ ((row&3)<<1), row&3 = gid&3
            const int colp = (((2 * kk + (tg >> 1)) ^ ((gid & 3) << 1)) << 2) + 2 * (tg & 1);
            uint32_t a[2][4];
            #pragma unroll
            for (int mi = 0; mi < 2; mi++) {
                int r = wm * 32 + mi * 16 + gid;
                float2 av0 = *(const float2*)&sm[aBase + r * 32 + colp];
                float2 av1 = *(const float2*)&sm[aBase + (r + 8) * 32 + colp];
                a[mi][0] = __float_as_uint(av0.x);
                a[mi][1] = __float_as_uint(av1.x);
                a[mi][2] = __float_as_uint(av0.y);
                a[mi][3] = __float_as_uint(av1.y);
            }
            #pragma unroll
            for (int ni = 0; ni < 8; ni++) {
                int n = wn * 64 + ni * 8 + gid;
                float2 bv = *(const float2*)&sm[bBase + n * 32 + colp];
                uint32_t b[2] = { __float_as_uint(bv.x), __float_as_uint(bv.y) };
                mma_tf32(c[0][ni], a[0], b);
                mma_tf32(c[1][ni], a[1], b);
            }
        }

        if ((g & 7) == 7) {
            const int nt = g >> 3;
            #pragma unroll
            for (int mi = 0; mi < 2; mi++)
                #pragma unroll
                for (int ni = 0; ni < 8; ni++) {
                    int cc = wn * 64 + ni * 8 + tg * 2;
                    int kl = nt * 256 + cc;
                    int kg = half * 512 + kl;
                    float q0 = sm[SQ(kl)], q1 = sm[SQ(kl + 1)];
                    float s0 = 2.0f * c[mi][ni][0] - q0;
                    float s1 = 2.0f * c[mi][ni][1] - q1;
                    float s2 = 2.0f * c[mi][ni][2] - q0;
                    float s3 = 2.0f * c[mi][ni][3] - q1;
                    FOLD(mi * 2 + 0, s0, kg);
                    FOLD(mi * 2 + 0, s1, kg + 1);
                    FOLD(mi * 2 + 1, s2, kg);
                    FOLD(mi * 2 + 1, s3, kg + 1);
                    #pragma unroll
                    for (int v = 0; v < 4; v++) c[mi][ni][v] = 0.0f;
                }
        }
    }

    // write 2 candidates per owned (row, owner); owner = wn*4+tg (16 owners)
    const int owner = wn * 4 + tg;
    #pragma unroll
    for (int s = 0; s < 4; s++) {
        int row = row0 + wm * 32 + (s >> 1) * 16 + (s & 1) * 8 + gid;
        size_t base = (size_t)row * 64 + half * 32 + owner * 2;
        g_cand[base]     = ti[s][0];  g_cand_s[base]     = ts[s][0];
        g_cand[base + 1] = ti[s][1];  g_cand_s[base + 1] = ts[s][1];
    }
}

// ---------------- exact select (fp64, margin-filtered) + update ----------------
__global__ void rvq_select_update(const float* __restrict__ cbs,
                                  float* __restrict__ codes_out, int q) {
    __shared__ float sApprox[64];
    __shared__ double sS[64];
    __shared__ int sK;
    __shared__ float red[8];
    __shared__ float sMax;
    const int n = blockIdx.x, tid = threadIdx.x;
    const int w = tid >> 5, lane = tid & 31;
    const float* __restrict__ cb = cbs + (size_t)q * BINS * DIM;

    if (tid < 64) {
        sApprox[tid] = g_cand_s[(size_t)n * 64 + tid];
        sS[tid] = -1e300;
    }
    __syncthreads();
    if (tid < 32) {
        float a = fmaxf(sApprox[tid], sApprox[tid + 32]);
        #pragma unroll
        for (int o = 16; o > 0; o >>= 1) a = fmaxf(a, __shfl_down_sync(0xffffffffu, a, o));
        if (tid == 0) sMax = a;
    }
    __syncthreads();

    const float thr = sMax - 0.3f;
    #pragma unroll 1
    for (int c8 = 0; c8 < 8; c8++) {
        const int ci = w * 8 + c8;
        if (sApprox[ci] >= thr) {
            const int cand = g_cand[(size_t)n * 64 + ci];
            const float* r = g_res + (size_t)n * DIM;
            const float* c = cb + (size_t)cand * DIM;
            double dot = 0.0, sq = 0.0;
            #pragma unroll
            for (int d = lane; d < DIM; d += 32) {
                double rv = r[d], cv = c[invD(d)];
                dot += rv * cv; sq += cv * cv;
            }
            #pragma unroll
            for (int o = 16; o > 0; o >>= 1) {
                dot += __shfl_down_sync(0xffffffffu, dot, o);
                sq  += __shfl_down_sync(0xffffffffu, sq, o);
            }
            if (lane == 0) sS[ci] = 2.0 * dot - sq;
        }
    }
    __syncthreads();
    if (tid == 0) {
        double best = -1e301; int bk = 1 << 30;
        #pragma unroll
        for (int j = 0; j < 64; j++) {
            double s = sS[j];
            int k = g_cand[(size_t)n * 64 + j];
            if (s > best || (s == best && k < bk)) { best = s; bk = k; }
        }
        sK = bk;
    }
    __syncthreads();

    const int k = sK;
    const int od = invD(tid);
    const float qv = cb[(size_t)k * DIM + od];
    const size_t off = (size_t)n * DIM + tid;
    const float rn = g_res[off] - qv;
    g_res[off] = rn;
    if (q == 0) g_acc[(size_t)n * DIM + od] = qv;
    else        g_acc[(size_t)n * DIM + od] += qv;

    float sq2 = rn * rn;
    #pragma unroll
    for (int o = 16; o > 0; o >>= 1) sq2 += __shfl_down_sync(0xffffffffu, sq2, o);
    if (lane == 0) red[w] = sq2;
    __syncthreads();
    if (tid == 0) {
        float tot = 0.0f;
        #pragma unroll
        for (int ww = 0; ww < 8; ww++) tot += red[ww];
        g_partial[q * NN + n] = tot;
        codes_out[q * NN + n] = (float)k;
    }
}

// ---------------- finalize: g_acc (N,D natural) -> out (B,D,T) ----------------
__global__ void rvq_finalize(float* __restrict__ out) {
    __shared__ float s[32][33];
    int b = blockIdx.z, d0 = blockIdx.y * 32, t0 = blockIdx.x * 32;
    int tx = threadIdx.x, ty = threadIdx.y;
    int t = t0 + ty;
    if (t < TT) s[ty][tx] = g_acc[((size_t)(b * TT + t)) * DIM + d0 + tx];
    __syncthreads();
    int t2 = t0 + tx;
    if (t2 < TT) out[((size_t)b * DIM + d0 + ty) * TT + t2] = s[tx][ty];
}

// ---------------- penalty ----------------
__global__ void rvq_penalty(float* __restrict__ out) {
    __shared__ float red[8];
    const int tid = threadIdx.x;
    float s = 0.0f;
    for (int i = tid; i < NQ * NN; i += 256) s += g_partial[i];
    #pragma unroll
    for (int o = 16; o > 0; o >>= 1) s += __shfl_down_sync(0xffffffffu, s, o);
    if ((tid & 31) == 0) red[tid >> 5] = s;
    __syncthreads();
    if (tid == 0) {
        float tot = 0.0f;
        #pragma unroll
        for (int w = 0; w < 8; w++) tot += red[w];
        out[(size_t)BB * DIM * TT + (size_t)NQ * NN] =
            tot / ((float)NQ * (float)NN * (float)DIM);
    }
}

// ---------------- launch ----------------
extern "C" void kernel_launch(void* const* d_in, const int* in_sizes, int n_in,
                              void* d_out, int out_size) {
    const float* x   = (const float*)d_in[0];
    const float* cbs = (const float*)d_in[1];
    float* out = (float*)d_out;
    float* codes_out = out + (size_t)BB * DIM * TT;

    cudaFuncSetAttribute(rvq_argmax_tc,
                         cudaFuncAttributeMaxDynamicSharedMemorySize, SMEM_BYTES);

    dim3 tb(32, 32);
    rvq_init<<<dim3(47, 8, 17), tb>>>(x);
    rvq_cbsq<<<1024, 256>>>(cbs);
    rvq_cbperm<<<(NQ * BINS * DIM + 255) / 256, 256>>>(cbs);

    for (int q = 0; q < NQ; q++) {
        rvq_argmax_tc<<<NTILE * 2, 512, SMEM_BYTES>>>(q);
        rvq_select_update<<<NN, 256>>>(cbs, codes_out, q);
    }

    rvq_finalize<<<dim3(47, 8, 16), tb>>>(out);
    rvq_penalty<<<1, 256>>>(out);
}

// round 13
// speedup vs baseline: 1.8382x; 1.5606x over previous
#include <cuda_runtime.h>
#include <cuda_bf16.h>
#include <cstdint>
#include <float.h>

#define NQ    8
#define BINS  1024
#define DIM   256
#define BB    16
#define TT    1500
#define NN    (BB * TT)
#define NPAD  24064
#define NTILE 188

// device scratch
__device__ float g_res[NPAD * DIM];          // residual, D-permuted within 8-groups
__device__ float g_acc[NPAD * DIM];          // natural D order
__device__ float g_cbp[NQ * BINS * DIM];     // permuted codebook copy
__device__ int   g_cand[NPAD * 64];
__device__ float g_cand_s[NPAD * 64];
__device__ float g_cbsq[NQ * BINS];
__device__ float g_partial[NQ * NN];

// D permutation within each 8-group
__device__ __forceinline__ int permD(int o) { return (o & ~7) | ((o & 3) << 1) | ((o & 4) >> 2); }
__device__ __forceinline__ int invD(int p)  { return (p & ~7) | ((p & 1) << 2) | ((p & 6) >> 1); }

// ---------------- helpers ----------------
__device__ __forceinline__ uint32_t smem_u32(const void* p) {
    uint32_t a;
    asm("{ .reg .u64 t; cvta.to.shared.u64 t, %1; cvt.u32.u64 %0, t; }" : "=r"(a) : "l"(p));
    return a;
}
__device__ __forceinline__ void cp_async16(uint32_t dst, const void* src) {
    asm volatile("cp.async.cg.shared.global [%0], [%1], 16;" :: "r"(dst), "l"(src) : "memory");
}
#define CP_COMMIT() asm volatile("cp.async.commit_group;" ::: "memory")
#define CP_WAIT1()  asm volatile("cp.async.wait_group 1;" ::: "memory")

__device__ __forceinline__ void mma_tf32(float* c, const uint32_t* a, const uint32_t* b) {
    asm volatile(
        "mma.sync.aligned.m16n8k8.row.col.f32.tf32.tf32.f32 "
        "{%0,%1,%2,%3}, {%4,%5,%6,%7}, {%8,%9}, {%0,%1,%2,%3};"
        : "+f"(c[0]), "+f"(c[1]), "+f"(c[2]), "+f"(c[3])
        : "r"(a[0]), "r"(a[1]), "r"(a[2]), "r"(a[3]), "r"(b[0]), "r"(b[1]));
}

// smem floats: A[3][128][32] @0 (12288), B[3][256][32] @12288 (24576), cbsq[512] @36864
#define SA_OFF(s)   ((s) * 4096)
#define SB_OFF(s)   (12288 + (s) * 8192)
#define SQ(i)       (36864 + (i))
#define SMEM_BYTES  (37376 * 4)

// ---------------- init: x (B,D,T) -> g_res (N, permD); z==16 slice zeroes pad ----------------
__global__ void rvq_init(const float* __restrict__ x) {
    __shared__ float s[32][33];
    if (blockIdx.z == 16) {
        int idx = (blockIdx.y * 47 + blockIdx.x) * 1024 + threadIdx.y * 32 + threadIdx.x;
        if (idx < (NPAD - NN) * DIM) g_res[(size_t)NN * DIM + idx] = 0.0f;
        return;
    }
    int b = blockIdx.z, d0 = blockIdx.y * 32, t0 = blockIdx.x * 32;
    int tx = threadIdx.x, ty = threadIdx.y;
    int t = t0 + tx;
    if (t < TT) s[ty][tx] = x[((size_t)b * DIM + d0 + ty) * TT + t];
    __syncthreads();
    int t2 = t0 + ty;
    if (t2 < TT)
        g_res[((size_t)(b * TT + t2)) * DIM + d0 + permD(tx)] = s[tx][ty];
}

// ---------------- cbsq + permuted codebook copy ----------------
__global__ void rvq_cbsq(const float* __restrict__ cb) {
    int warp = (blockIdx.x * blockDim.x + threadIdx.x) >> 5;
    int lane = threadIdx.x & 31;
    if (warp >= NQ * BINS) return;
    const float* row = cb + (size_t)warp * DIM;
    float s = 0.0f;
    for (int d = lane; d < DIM; d += 32) { float c = row[d]; s += c * c; }
    #pragma unroll
    for (int o = 16; o > 0; o >>= 1) s += __shfl_down_sync(0xffffffffu, s, o);
    if (lane == 0) g_cbsq[warp] = s;
}

__global__ void rvq_cbperm(const float* __restrict__ cbs) {
    size_t i = (size_t)blockIdx.x * blockDim.x + threadIdx.x;
    if (i >= (size_t)NQ * BINS * DIM) return;
    int d = (int)(i & 255);
    g_cbp[(i - d) + permD(d)] = cbs[i];
}

// ---------------- tf32 tensor-core argmax: 128 rows x 512 bins per CTA ----------------
// 512 threads, 16 warps (4m x 4n), warp tile 32x64, 64 accums/thread; top-2 per owner.
// chunk g = nt*8 + kc, nt in {0,1} covers 256 bins; 3-slot smem pipeline.
// Bank-conflict-free swizzle: group c of row r stored at physical group c ^ ((r&3)<<1).
__global__ __launch_bounds__(512, 1) void rvq_argmax_tc(int q) {
    extern __shared__ float sm[];
    const uint32_t sb = smem_u32(sm);
    const int tid = threadIdx.x;
    const int lane = tid & 31, wid = tid >> 5;
    const int gid = lane >> 2, tg = lane & 3;
    const int wm = wid & 3, wn = wid >> 2;        // warp grid 4 (m) x 4 (n), warp tile 32x64
    const int mtile = blockIdx.x >> 1, half = blockIdx.x & 1;
    const int row0 = mtile * 128;
    const float* __restrict__ cbp = g_cbp + ((size_t)q * BINS + half * 512) * DIM;

    sm[SQ(tid)] = g_cbsq[q * BINS + half * 512 + tid];

    // prefetch mapping: A rows ur, ur+64; B rows ur, ur+64, ur+128, ur+192
    const int ur = tid >> 3, useg = tid & 7;      // ur 0..63
    const float* aG = g_res + (size_t)(row0 + ur) * DIM + useg * 4;
    const float* bG = cbp + (size_t)ur * DIM + useg * 4;
    // physical group = useg ^ ((ur&3)<<1); rows +64k share ur&3 -> same offset
    const uint32_t wOff = (uint32_t)(ur * 32 + ((useg ^ ((ur & 3) << 1)) << 2)) * 4u;

#define PREF(pg_) do { \
    const int slot_ = (pg_) % 3; \
    const uint32_t dA_ = sb + (uint32_t)SA_OFF(slot_) * 4u + wOff; \
    const uint32_t dB_ = sb + (uint32_t)SB_OFF(slot_) * 4u + wOff; \
    const float* sA_ = aG + ((pg_) & 7) * 32; \
    const float* sB_ = bG + (size_t)((pg_) >> 3) * (256 * DIM) + ((pg_) & 7) * 32; \
    cp_async16(dA_,          sA_); \
    cp_async16(dA_ + 8192u,  sA_ + 64 * DIM); \
    cp_async16(dB_,          sB_); \
    cp_async16(dB_ + 8192u,  sB_ + 64 * DIM); \
    cp_async16(dB_ + 16384u, sB_ + 128 * DIM); \
    cp_async16(dB_ + 24576u, sB_ + 192 * DIM); \
    CP_COMMIT(); \
} while (0)

    float ts[4][2]; int ti[4][2];
    #pragma unroll
    for (int s = 0; s < 4; s++) {
        ts[s][0] = -FLT_MAX; ts[s][1] = -FLT_MAX;
        ti[s][0] = 0; ti[s][1] = 0;
    }

    float c[2][8][4];
    #pragma unroll
    for (int mi = 0; mi < 2; mi++)
        #pragma unroll
        for (int ni = 0; ni < 8; ni++)
            #pragma unroll
            for (int v = 0; v < 4; v++) c[mi][ni][v] = 0.0f;

#define FOLD(slot, sc, kg) do { \
    if ((sc) > ts[slot][0]) { \
        ts[slot][1] = ts[slot][0]; ti[slot][1] = ti[slot][0]; \
        ts[slot][0] = (sc); ti[slot][0] = (kg); \
    } else if ((sc) > ts[slot][1]) { ts[slot][1] = (sc); ti[slot][1] = (kg); } \
} while (0)

    PREF(0);
    PREF(1);

    #pragma unroll 1
    for (int g = 0; g < 16; g++) {
        CP_WAIT1();            // chunk g landed (g+1 still pending)
        __syncthreads();       // visibility; slot (g+2)%3 fully consumed (iter g-1)
        if (g + 2 < 16) { PREF(g + 2); } else { CP_COMMIT(); }

        const int buf = g % 3;
        const uint32_t aBase = (uint32_t)SA_OFF(buf);
        const uint32_t bBase = (uint32_t)SB_OFF(buf);
        #pragma unroll
        for (int kk = 0; kk < 4; kk++) {
            // logical group c = 2kk + (tg>>1); physical = c ^ ((row&3)<<1), row&3 = gid&3
            const int colp = (((2 * kk + (tg >> 1)) ^ ((gid & 3) << 1)) << 2) + 2 * (tg & 1);
            uint32_t a[2][4];
            #pragma unroll
            for (int mi = 0; mi < 2; mi++) {
                int r = wm * 32 + mi * 16 + gid;
                float2 av0 = *(const float2*)&sm[aBase + r * 32 + colp];
                float2 av1 = *(const float2*)&sm[aBase + (r + 8) * 32 + colp];
                a[mi][0] = __float_as_uint(av0.x);
                a[mi][1] = __float_as_uint(av1.x);
                a[mi][2] = __float_as_uint(av0.y);
                a[mi][3] = __float_as_uint(av1.y);
            }
            #pragma unroll
            for (int ni = 0; ni < 8; ni++) {
                int n = wn * 64 + ni * 8 + gid;
                float2 bv = *(const float2*)&sm[bBase + n * 32 + colp];
                uint32_t b[2] = { __float_as_uint(bv.x), __float_as_uint(bv.y) };
                mma_tf32(c[0][ni], a[0], b);
                mma_tf32(c[1][ni], a[1], b);
            }
        }

        if ((g & 7) == 7) {
            const int nt = g >> 3;
            #pragma unroll
            for (int mi = 0; mi < 2; mi++)
                #pragma unroll
                for (int ni = 0; ni < 8; ni++) {
                    int cc = wn * 64 + ni * 8 + tg * 2;
                    int kl = nt * 256 + cc;
                    int kg = half * 512 + kl;
                    float q0 = sm[SQ(kl)], q1 = sm[SQ(kl + 1)];
                    float s0 = 2.0f * c[mi][ni][0] - q0;
                    float s1 = 2.0f * c[mi][ni][1] - q1;
                    float s2 = 2.0f * c[mi][ni][2] - q0;
                    float s3 = 2.0f * c[mi][ni][3] - q1;
                    FOLD(mi * 2 + 0, s0, kg);
                    FOLD(mi * 2 + 0, s1, kg + 1);
                    FOLD(mi * 2 + 1, s2, kg);
                    FOLD(mi * 2 + 1, s3, kg + 1);
                    #pragma unroll
                    for (int v = 0; v < 4; v++) c[mi][ni][v] = 0.0f;
                }
        }
    }

    // write 2 candidates per owned (row, owner); owner = wn*4+tg (16 owners)
    const int owner = wn * 4 + tg;
    #pragma unroll
    for (int s = 0; s < 4; s++) {
        int row = row0 + wm * 32 + (s >> 1) * 16 + (s & 1) * 8 + gid;
        size_t base = (size_t)row * 64 + half * 32 + owner * 2;
        g_cand[base]     = ti[s][0];  g_cand_s[base]     = ts[s][0];
        g_cand[base + 1] = ti[s][1];  g_cand_s[base + 1] = ts[s][1];
    }
}

// ---------------- select + update: warp per row, ballot-compacted exact rescue ----------------
// If only one candidate lies within 0.3 of the approx max (tf32 err <= ~0.05),
// it is provably the exact argmax -> skip fp64. Else rescore survivors exactly.
__global__ __launch_bounds__(256) void rvq_select_update(const float* __restrict__ cbs,
                                                         float* __restrict__ codes_out, int q) {
    const int lane = threadIdx.x & 31;
    const int n = blockIdx.x * 8 + (threadIdx.x >> 5);   // warp per row
    const float* __restrict__ cb = cbs + (size_t)q * BINS * DIM;

    // load 64 candidate scores (2 per lane) and find max
    const size_t cbase = (size_t)n * 64;
    float s0 = g_cand_s[cbase + lane];
    float s1 = g_cand_s[cbase + 32 + lane];
    float mx = fmaxf(s0, s1);
    #pragma unroll
    for (int o = 16; o > 0; o >>= 1) mx = fmaxf(mx, __shfl_xor_sync(0xffffffffu, mx, o));

    const float thr = mx - 0.3f;
    unsigned m0 = __ballot_sync(0xffffffffu, s0 >= thr);
    unsigned m1 = __ballot_sync(0xffffffffu, s1 >= thr);

    int k;
    if (__popc(m0) + __popc(m1) == 1) {
        // unique survivor == exact winner
        int ci = m0 ? (__ffs(m0) - 1) : (31 + __ffs(m1));
        k = g_cand[cbase + ci];
    } else {
        // exact fp64 rescore of all survivors; fused score = sum(2*r*c - c*c)
        const float* r = g_res + (size_t)n * DIM;
        unsigned long long m = ((unsigned long long)m1 << 32) | (unsigned long long)m0;
        double best = -1e300; int bk = 1 << 30;
        while (m) {
            int ci = __ffsll((long long)m) - 1;
            m &= m - 1;
            int cand = g_cand[cbase + ci];
            const float* c = cb + (size_t)cand * DIM;
            double sc = 0.0;
            #pragma unroll
            for (int j = 0; j < 8; j++) {
                int pp = lane + j * 32;
                double rv = r[pp], cv = c[invD(pp)];
                sc += cv * (2.0 * rv - cv);
            }
            #pragma unroll
            for (int o = 16; o > 0; o >>= 1)
                sc += __shfl_xor_sync(0xffffffffu, sc, o);
            if (sc > best || (sc == best && cand < bk)) { best = sc; bk = cand; }
        }
        k = bk;
    }

    // update: 8 elems per lane; loss partial
    const float* ck = cb + (size_t)k * DIM;
    float loss = 0.0f;
    #pragma unroll
    for (int j = 0; j < 8; j++) {
        int pp = lane + j * 32;
        int od = invD(pp);
        float qv = ck[od];
        size_t off = (size_t)n * DIM + pp;
        float rn = g_res[off] - qv;
        g_res[off] = rn;
        size_t aoff = (size_t)n * DIM + od;
        if (q == 0) g_acc[aoff] = qv;
        else        g_acc[aoff] += qv;
        loss += rn * rn;
    }
    #pragma unroll
    for (int o = 16; o > 0; o >>= 1) loss += __shfl_down_sync(0xffffffffu, loss, o);
    if (lane == 0) {
        g_partial[q * NN + n] = loss;
        codes_out[q * NN + n] = (float)k;
    }
}

// ---------------- finalize: g_acc (N,D natural) -> out (B,D,T) ----------------
__global__ void rvq_finalize(float* __restrict__ out) {
    __shared__ float s[32][33];
    int b = blockIdx.z, d0 = blockIdx.y * 32, t0 = blockIdx.x * 32;
    int tx = threadIdx.x, ty = threadIdx.y;
    int t = t0 + ty;
    if (t < TT) s[ty][tx] = g_acc[((size_t)(b * TT + t)) * DIM + d0 + tx];
    __syncthreads();
    int t2 = t0 + tx;
    if (t2 < TT) out[((size_t)b * DIM + d0 + ty) * TT + t2] = s[tx][ty];
}

// ---------------- penalty ----------------
__global__ void rvq_penalty(float* __restrict__ out) {
    __shared__ float red[8];
    const int tid = threadIdx.x;
    float s = 0.0f;
    for (int i = tid; i < NQ * NN; i += 256) s += g_partial[i];
    #pragma unroll
    for (int o = 16; o > 0; o >>= 1) s += __shfl_down_sync(0xffffffffu, s, o);
    if ((tid & 31) == 0) red[tid >> 5] = s;
    __syncthreads();
    if (tid == 0) {
        float tot = 0.0f;
        #pragma unroll
        for (int w = 0; w < 8; w++) tot += red[w];
        out[(size_t)BB * DIM * TT + (size_t)NQ * NN] =
            tot / ((float)NQ * (float)NN * (float)DIM);
    }
}

// ---------------- launch ----------------
extern "C" void kernel_launch(void* const* d_in, const int* in_sizes, int n_in,
                              void* d_out, int out_size) {
    const float* x   = (const float*)d_in[0];
    const float* cbs = (const float*)d_in[1];
    float* out = (float*)d_out;
    float* codes_out = out + (size_t)BB * DIM * TT;

    cudaFuncSetAttribute(rvq_argmax_tc,
                         cudaFuncAttributeMaxDynamicSharedMemorySize, SMEM_BYTES);

    dim3 tb(32, 32);
    rvq_init<<<dim3(47, 8, 17), tb>>>(x);
    rvq_cbsq<<<1024, 256>>>(cbs);
    rvq_cbperm<<<(NQ * BINS * DIM + 255) / 256, 256>>>(cbs);

    for (int q = 0; q < NQ; q++) {
        rvq_argmax_tc<<<NTILE * 2, 512, SMEM_BYTES>>>(q);
        rvq_select_update<<<NN / 8, 256>>>(cbs, codes_out, q);
    }

    rvq_finalize<<<dim3(47, 8, 16), tb>>>(out);
    rvq_penalty<<<1, 256>>>(out);
}

// round 14
// speedup vs baseline: 1.8822x; 1.0240x over previous
#include <cuda_runtime.h>
#include <cuda_bf16.h>
#include <cstdint>
#include <float.h>

#define NQ    8
#define BINS  1024
#define DIM   256
#define BB    16
#define TT    1500
#define NN    (BB * TT)
#define NPAD  24064
#define NTILE 188

// device scratch
__device__ float g_res[NPAD * DIM];          // residual, D-permuted within 8-groups
__device__ float g_acc[NPAD * DIM];          // natural D order
__device__ float g_cbp[NQ * BINS * DIM];     // permuted codebook copy
__device__ int   g_cand[NPAD * 32];
__device__ float g_cand_s[NPAD * 32];
__device__ float g_cbsq[NQ * BINS];
__device__ float g_partial[NQ * NN];

// D permutation within each 8-group
__device__ __forceinline__ int permD(int o) { return (o & ~7) | ((o & 3) << 1) | ((o & 4) >> 2); }
__device__ __forceinline__ int invD(int p)  { return (p & ~7) | ((p & 1) << 2) | ((p & 6) >> 1); }

// ---------------- helpers ----------------
__device__ __forceinline__ uint32_t smem_u32(const void* p) {
    uint32_t a;
    asm("{ .reg .u64 t; cvta.to.shared.u64 t, %1; cvt.u32.u64 %0, t; }" : "=r"(a) : "l"(p));
    return a;
}
__device__ __forceinline__ void cp_async16(uint32_t dst, const void* src) {
    asm volatile("cp.async.cg.shared.global [%0], [%1], 16;" :: "r"(dst), "l"(src) : "memory");
}
#define CP_COMMIT() asm volatile("cp.async.commit_group;" ::: "memory")
#define CP_WAIT1()  asm volatile("cp.async.wait_group 1;" ::: "memory")

__device__ __forceinline__ void mma_tf32(float* c, const uint32_t* a, const uint32_t* b) {
    asm volatile(
        "mma.sync.aligned.m16n8k8.row.col.f32.tf32.tf32.f32 "
        "{%0,%1,%2,%3}, {%4,%5,%6,%7}, {%8,%9}, {%0,%1,%2,%3};"
        : "+f"(c[0]), "+f"(c[1]), "+f"(c[2]), "+f"(c[3])
        : "r"(a[0]), "r"(a[1]), "r"(a[2]), "r"(a[3]), "r"(b[0]), "r"(b[1]));
}

// smem floats: A[3][128][32] @0 (12288), B[3][128][32] @12288 (12288), cbsq[512] @24576
// total 25088 floats = 100352 bytes -> 2 CTAs per SM
#define SA_OFF(s)   ((s) * 4096)
#define SB_OFF(s)   (12288 + (s) * 4096)
#define SQ(i)       (24576 + (i))
#define SMEM_BYTES  (25088 * 4)

// ---------------- init: x (B,D,T) -> g_res (N, permD); z==16 slice zeroes pad ----------------
__global__ void rvq_init(const float* __restrict__ x) {
    __shared__ float s[32][33];
    if (blockIdx.z == 16) {
        int idx = (blockIdx.y * 47 + blockIdx.x) * 1024 + threadIdx.y * 32 + threadIdx.x;
        if (idx < (NPAD - NN) * DIM) g_res[(size_t)NN * DIM + idx] = 0.0f;
        return;
    }
    int b = blockIdx.z, d0 = blockIdx.y * 32, t0 = blockIdx.x * 32;
    int tx = threadIdx.x, ty = threadIdx.y;
    int t = t0 + tx;
    if (t < TT) s[ty][tx] = x[((size_t)b * DIM + d0 + ty) * TT + t];
    __syncthreads();
    int t2 = t0 + ty;
    if (t2 < TT)
        g_res[((size_t)(b * TT + t2)) * DIM + d0 + permD(tx)] = s[tx][ty];
}

// ---------------- cbsq + permuted codebook copy ----------------
__global__ void rvq_cbsq(const float* __restrict__ cb) {
    int warp = (blockIdx.x * blockDim.x + threadIdx.x) >> 5;
    int lane = threadIdx.x & 31;
    if (warp >= NQ * BINS) return;
    const float* row = cb + (size_t)warp * DIM;
    float s = 0.0f;
    for (int d = lane; d < DIM; d += 32) { float c = row[d]; s += c * c; }
    #pragma unroll
    for (int o = 16; o > 0; o >>= 1) s += __shfl_down_sync(0xffffffffu, s, o);
    if (lane == 0) g_cbsq[warp] = s;
}

__global__ void rvq_cbperm(const float* __restrict__ cbs) {
    size_t i = (size_t)blockIdx.x * blockDim.x + threadIdx.x;
    if (i >= (size_t)NQ * BINS * DIM) return;
    int d = (int)(i & 255);
    g_cbp[(i - d) + permD(d)] = cbs[i];
}

// ---------------- tf32 tensor-core argmax: 128 rows x 512 bins per CTA ----------------
// 256 threads, 8 warps (4m x 2n), warp tile 32x64, 64 accums/thread; top-2 per owner.
// chunk g = nt*8 + kc, nt in 0..3 covers 128 bins each; 3-slot smem pipeline; 2 CTAs/SM.
// Bank-conflict-free swizzle: group c of row r stored at physical group c ^ ((r&3)<<1).
__global__ __launch_bounds__(256, 2) void rvq_argmax_tc(int q) {
    extern __shared__ float sm[];
    const uint32_t sb = smem_u32(sm);
    const int tid = threadIdx.x;
    const int lane = tid & 31, wid = tid >> 5;
    const int gid = lane >> 2, tg = lane & 3;
    const int wm = wid & 3, wn = wid >> 2;        // warp grid 4 (m) x 2 (n), warp tile 32x64
    const int mtile = blockIdx.x >> 1, half = blockIdx.x & 1;
    const int row0 = mtile * 128;
    const float* __restrict__ cbp = g_cbp + ((size_t)q * BINS + half * 512) * DIM;

    for (int i = tid; i < 512; i += 256) sm[SQ(i)] = g_cbsq[q * BINS + half * 512 + i];

    // prefetch mapping: A rows ur+{0,32,64,96}; B rows ur+{0,32,64,96}; 16B unit useg
    const int ur = tid >> 3, useg = tid & 7;      // ur 0..31
    const float* aG = g_res + (size_t)(row0 + ur) * DIM + useg * 4;
    const float* bG = cbp + (size_t)ur * DIM + useg * 4;
    // physical group = useg ^ ((ur&3)<<1); rows +32k share ur&3 -> same offset
    const uint32_t wOff = (uint32_t)(ur * 32 + ((useg ^ ((ur & 3) << 1)) << 2)) * 4u;

#define PREF(pg_) do { \
    const int slot_ = (pg_) % 3; \
    const uint32_t dA_ = sb + (uint32_t)SA_OFF(slot_) * 4u + wOff; \
    const uint32_t dB_ = sb + (uint32_t)SB_OFF(slot_) * 4u + wOff; \
    const float* sA_ = aG + ((pg_) & 7) * 32; \
    const float* sB_ = bG + (size_t)((pg_) >> 3) * (128 * DIM) + ((pg_) & 7) * 32; \
    cp_async16(dA_,          sA_); \
    cp_async16(dA_ + 4096u,  sA_ + 32 * DIM); \
    cp_async16(dA_ + 8192u,  sA_ + 64 * DIM); \
    cp_async16(dA_ + 12288u, sA_ + 96 * DIM); \
    cp_async16(dB_,          sB_); \
    cp_async16(dB_ + 4096u,  sB_ + 32 * DIM); \
    cp_async16(dB_ + 8192u,  sB_ + 64 * DIM); \
    cp_async16(dB_ + 12288u, sB_ + 96 * DIM); \
    CP_COMMIT(); \
} while (0)

    float ts[4][2]; int ti[4][2];
    #pragma unroll
    for (int s = 0; s < 4; s++) {
        ts[s][0] = -FLT_MAX; ts[s][1] = -FLT_MAX;
        ti[s][0] = 0; ti[s][1] = 0;
    }

    float c[2][8][4];
    #pragma unroll
    for (int mi = 0; mi < 2; mi++)
        #pragma unroll
        for (int ni = 0; ni < 8; ni++)
            #pragma unroll
            for (int v = 0; v < 4; v++) c[mi][ni][v] = 0.0f;

#define FOLD(slot, sc, kg) do { \
    if ((sc) > ts[slot][0]) { \
        ts[slot][1] = ts[slot][0]; ti[slot][1] = ti[slot][0]; \
        ts[slot][0] = (sc); ti[slot][0] = (kg); \
    } else if ((sc) > ts[slot][1]) { ts[slot][1] = (sc); ti[slot][1] = (kg); } \
} while (0)

    PREF(0);
    PREF(1);

    #pragma unroll 1
    for (int g = 0; g < 32; g++) {
        CP_WAIT1();            // chunk g landed (g+1 still pending)
        __syncthreads();       // visibility; slot (g+2)%3 fully consumed (iter g-1)
        if (g + 2 < 32) { PREF(g + 2); } else { CP_COMMIT(); }

        const int buf = g % 3;
        const uint32_t aBase = (uint32_t)SA_OFF(buf);
        const uint32_t bBase = (uint32_t)SB_OFF(buf);
        #pragma unroll
        for (int kk = 0; kk < 4; kk++) {
            // logical group c = 2kk + (tg>>1); physical = c ^ ((row&3)<<1), row&3 = gid&3
            const int colp = (((2 * kk + (tg >> 1)) ^ ((gid & 3) << 1)) << 2) + 2 * (tg & 1);
            uint32_t a[2][4];
            #pragma unroll
            for (int mi = 0; mi < 2; mi++) {
                int r = wm * 32 + mi * 16 + gid;
                float2 av0 = *(const float2*)&sm[aBase + r * 32 + colp];
                float2 av1 = *(const float2*)&sm[aBase + (r + 8) * 32 + colp];
                a[mi][0] = __float_as_uint(av0.x);
                a[mi][1] = __float_as_uint(av1.x);
                a[mi][2] = __float_as_uint(av0.y);
                a[mi][3] = __float_as_uint(av1.y);
            }
            #pragma unroll
            for (int ni = 0; ni < 8; ni++) {
                int n = wn * 64 + ni * 8 + gid;
                float2 bv = *(const float2*)&sm[bBase + n * 32 + colp];
                uint32_t b[2] = { __float_as_uint(bv.x), __float_as_uint(bv.y) };
                mma_tf32(c[0][ni], a[0], b);
                mma_tf32(c[1][ni], a[1], b);
            }
        }

        if ((g & 7) == 7) {
            const int nt = g >> 3;
            #pragma unroll
            for (int mi = 0; mi < 2; mi++)
                #pragma unroll
                for (int ni = 0; ni < 8; ni++) {
                    int cc = wn * 64 + ni * 8 + tg * 2;
                    int kl = nt * 128 + cc;
                    int kg = half * 512 + kl;
                    float q0 = sm[SQ(kl)], q1 = sm[SQ(kl + 1)];
                    float s0 = 2.0f * c[mi][ni][0] - q0;
                    float s1 = 2.0f * c[mi][ni][1] - q1;
                    float s2 = 2.0f * c[mi][ni][2] - q0;
                    float s3 = 2.0f * c[mi][ni][3] - q1;
                    FOLD(mi * 2 + 0, s0, kg);
                    FOLD(mi * 2 + 0, s1, kg + 1);
                    FOLD(mi * 2 + 1, s2, kg);
                    FOLD(mi * 2 + 1, s3, kg + 1);
                    #pragma unroll
                    for (int v = 0; v < 4; v++) c[mi][ni][v] = 0.0f;
                }
        }
    }

    // write 2 candidates per owned (row, owner); owner = wn*4+tg (8 owners)
    const int owner = wn * 4 + tg;
    #pragma unroll
    for (int s = 0; s < 4; s++) {
        int row = row0 + wm * 32 + (s >> 1) * 16 + (s & 1) * 8 + gid;
        size_t base = (size_t)row * 32 + half * 16 + owner * 2;
        g_cand[base]     = ti[s][0];  g_cand_s[base]     = ts[s][0];
        g_cand[base + 1] = ti[s][1];  g_cand_s[base + 1] = ts[s][1];
    }
}

// ---------------- select + update: warp per row, ballot-compacted exact rescue ----------------
// If only one candidate lies within 0.3 of the approx max (tf32 err <= ~0.05),
// it is provably the exact argmax -> skip fp64. Else rescore survivors exactly.
__global__ __launch_bounds__(256) void rvq_select_update(const float* __restrict__ cbs,
                                                         float* __restrict__ codes_out, int q) {
    const int lane = threadIdx.x & 31;
    const int n = blockIdx.x * 8 + (threadIdx.x >> 5);   // warp per row
    const float* __restrict__ cb = cbs + (size_t)q * BINS * DIM;

    // load 32 candidate scores (1 per lane) and find max
    const size_t cbase = (size_t)n * 32;
    float s0 = g_cand_s[cbase + lane];
    float mx = s0;
    #pragma unroll
    for (int o = 16; o > 0; o >>= 1) mx = fmaxf(mx, __shfl_xor_sync(0xffffffffu, mx, o));

    const float thr = mx - 0.3f;
    unsigned m = __ballot_sync(0xffffffffu, s0 >= thr);

    int k;
    if (__popc(m) == 1) {
        // unique survivor == exact winner
        k = g_cand[cbase + (__ffs(m) - 1)];
    } else {
        // exact fp64 rescore of survivors; fused score = sum(c*(2r - c))
        const float* r = g_res + (size_t)n * DIM;
        double best = -1e300; int bk = 1 << 30;
        while (m) {
            int ci = __ffs(m) - 1;
            m &= m - 1;
            int cand = g_cand[cbase + ci];
            const float* c = cb + (size_t)cand * DIM;
            double sc = 0.0;
            #pragma unroll
            for (int j = 0; j < 8; j++) {
                int pp = lane + j * 32;
                double rv = r[pp], cv = c[invD(pp)];
                sc += cv * (2.0 * rv - cv);
            }
            #pragma unroll
            for (int o = 16; o > 0; o >>= 1)
                sc += __shfl_xor_sync(0xffffffffu, sc, o);
            if (sc > best || (sc == best && cand < bk)) { best = sc; bk = cand; }
        }
        k = bk;
    }

    // update: 8 elems per lane; loss partial
    const float* ck = cb + (size_t)k * DIM;
    float loss = 0.0f;
    #pragma unroll
    for (int j = 0; j < 8; j++) {
        int pp = lane + j * 32;
        int od = invD(pp);
        float qv = ck[od];
        size_t off = (size_t)n * DIM + pp;
        float rn = g_res[off] - qv;
        g_res[off] = rn;
        size_t aoff = (size_t)n * DIM + od;
        if (q == 0) g_acc[aoff] = qv;
        else        g_acc[aoff] += qv;
        loss += rn * rn;
    }
    #pragma unroll
    for (int o = 16; o > 0; o >>= 1) loss += __shfl_down_sync(0xffffffffu, loss, o);
    if (lane == 0) {
        g_partial[q * NN + n] = loss;
        codes_out[q * NN + n] = (float)k;
    }
}

// ---------------- finalize: g_acc (N,D natural) -> out (B,D,T) ----------------
__global__ void rvq_finalize(float* __restrict__ out) {
    __shared__ float s[32][33];
    int b = blockIdx.z, d0 = blockIdx.y * 32, t0 = blockIdx.x * 32;
    int tx = threadIdx.x, ty = threadIdx.y;
    int t = t0 + ty;
    if (t < TT) s[ty][tx] = g_acc[((size_t)(b * TT + t)) * DIM + d0 + tx];
    __syncthreads();
    int t2 = t0 + tx;
    if (t2 < TT) out[((size_t)b * DIM + d0 + ty) * TT + t2] = s[tx][ty];
}

// ---------------- penalty ----------------
__global__ void rvq_penalty(float* __restrict__ out) {
    __shared__ float red[8];
    const int tid = threadIdx.x;
    float s = 0.0f;
    for (int i = tid; i < NQ * NN; i += 256) s += g_partial[i];
    #pragma unroll
    for (int o = 16; o > 0; o >>= 1) s += __shfl_down_sync(0xffffffffu, s, o);
    if ((tid & 31) == 0) red[tid >> 5] = s;
    __syncthreads();
    if (tid == 0) {
        float tot = 0.0f;
        #pragma unroll
        for (int w = 0; w < 8; w++) tot += red[w];
        out[(size_t)BB * DIM * TT + (size_t)NQ * NN] =
            tot / ((float)NQ * (float)NN * (float)DIM);
    }
}

// ---------------- launch ----------------
extern "C" void kernel_launch(void* const* d_in, const int* in_sizes, int n_in,
                              void* d_out, int out_size) {
    const float* x   = (const float*)d_in[0];
    const float* cbs = (const float*)d_in[1];
    float* out = (float*)d_out;
    float* codes_out = out + (size_t)BB * DIM * TT;

    cudaFuncSetAttribute(rvq_argmax_tc,
                         cudaFuncAttributeMaxDynamicSharedMemorySize, SMEM_BYTES);

    dim3 tb(32, 32);
    rvq_init<<<dim3(47, 8, 17), tb>>>(x);
    rvq_cbsq<<<1024, 256>>>(cbs);
    rvq_cbperm<<<(NQ * BINS * DIM + 255) / 256, 256>>>(cbs);

    for (int q = 0; q < NQ; q++) {
        rvq_argmax_tc<<<NTILE * 2, 256, SMEM_BYTES>>>(q);
        rvq_select_update<<<NN / 8, 256>>>(cbs, codes_out, q);
    }

    rvq_finalize<<<dim3(47, 8, 16), tb>>>(out);
    rvq_penalty<<<1, 256>>>(out);
}

// round 15
// speedup vs baseline: 2.4243x; 1.2880x over previous
#include <cuda_runtime.h>
#include <cuda_bf16.h>
#include <cstdint>
#include <float.h>

#define NQ    8
#define BINS  1024
#define DIM   256
#define BB    16
#define TT    1500
#define NN    (BB * TT)
#define NPAD  24064
#define NTILE 188

// device scratch (all natural D order now — no permutation needed for bf16 k16 frags)
__device__ float          g_res[NPAD * DIM];
__device__ __nv_bfloat16  g_resh[NPAD * DIM];
__device__ float          g_acc[NPAD * DIM];
__device__ __nv_bfloat16  g_cbh[NQ * BINS * DIM];
__device__ int   g_cand[NPAD * 128];
__device__ float g_cand_s[NPAD * 128];
__device__ float g_cbsq[NQ * BINS];
__device__ float g_partial[NQ * NN];

// ---------------- helpers ----------------
__device__ __forceinline__ uint32_t smem_u32(const void* p) {
    uint32_t a;
    asm("{ .reg .u64 t; cvta.to.shared.u64 t, %1; cvt.u32.u64 %0, t; }" : "=r"(a) : "l"(p));
    return a;
}
__device__ __forceinline__ void cp_async16(uint32_t dst, const void* src) {
    asm volatile("cp.async.cg.shared.global [%0], [%1], 16;" :: "r"(dst), "l"(src) : "memory");
}
#define CP_COMMIT() asm volatile("cp.async.commit_group;" ::: "memory")
#define CP_WAIT1()  asm volatile("cp.async.wait_group 1;" ::: "memory")

__device__ __forceinline__ void mma_bf16(float* c, const uint32_t* a, const uint32_t* b) {
    asm volatile(
        "mma.sync.aligned.m16n8k16.row.col.f32.bf16.bf16.f32 "
        "{%0,%1,%2,%3}, {%4,%5,%6,%7}, {%8,%9}, {%0,%1,%2,%3};"
        : "+f"(c[0]), "+f"(c[1]), "+f"(c[2]), "+f"(c[3])
        : "r"(a[0]), "r"(a[1]), "r"(a[2]), "r"(a[3]), "r"(b[0]), "r"(b[1]));
}

// smem floats: A[3][128 rows x 32 words] @0 (12288), B[3][...] @12288, cbsq[512] @24576
// chunk = K=64 bf16 -> 128B rows. Swizzle: phys 16B-unit = unit ^ (row & 7).
#define SA_OFF(s)   ((s) * 4096)
#define SB_OFF(s)   (12288 + (s) * 4096)
#define SQ(i)       (24576 + (i))
#define SMEM_BYTES  (25088 * 4)

// ---------------- init: x (B,D,T) -> g_res/g_resh (N,D natural); z==16 zeroes pad ----------------
__global__ void rvq_init(const float* __restrict__ x) {
    __shared__ float s[32][33];
    if (blockIdx.z == 16) {
        int idx = (blockIdx.y * 47 + blockIdx.x) * 1024 + threadIdx.y * 32 + threadIdx.x;
        if (idx < (NPAD - NN) * DIM) {
            g_res[(size_t)NN * DIM + idx] = 0.0f;
            g_resh[(size_t)NN * DIM + idx] = __float2bfloat16(0.0f);
        }
        return;
    }
    int b = blockIdx.z, d0 = blockIdx.y * 32, t0 = blockIdx.x * 32;
    int tx = threadIdx.x, ty = threadIdx.y;
    int t = t0 + tx;
    if (t < TT) s[ty][tx] = x[((size_t)b * DIM + d0 + ty) * TT + t];
    __syncthreads();
    int t2 = t0 + ty;
    if (t2 < TT) {
        float v = s[tx][ty];
        size_t off = ((size_t)(b * TT + t2)) * DIM + d0 + tx;
        g_res[off] = v;
        g_resh[off] = __float2bfloat16(v);
    }
}

// ---------------- cbsq + bf16 codebook copy (natural layout) ----------------
__global__ void rvq_cbsq(const float* __restrict__ cb) {
    int warp = (blockIdx.x * blockDim.x + threadIdx.x) >> 5;
    int lane = threadIdx.x & 31;
    if (warp >= NQ * BINS) return;
    const float* row = cb + (size_t)warp * DIM;
    float s = 0.0f;
    for (int d = lane; d < DIM; d += 32) { float c = row[d]; s += c * c; }
    #pragma unroll
    for (int o = 16; o > 0; o >>= 1) s += __shfl_down_sync(0xffffffffu, s, o);
    if (lane == 0) g_cbsq[warp] = s;
}

__global__ void rvq_cbh(const float* __restrict__ cbs) {
    size_t i = (size_t)blockIdx.x * blockDim.x + threadIdx.x;
    if (i >= (size_t)NQ * BINS * DIM) return;
    g_cbh[i] = __float2bfloat16(cbs[i]);
}

// ---------------- bf16 tensor-core argmax: 128 rows x 512 bins per CTA ----------------
// 256 threads, 8 warps (4m x 2n), warp tile 32x64; chunk = 128 cols x K=64 (g = nt*4+kc).
// top-2 per owner per nt (8 owners * 2 * 4 nt * 2 halves = 128 candidates/row).
__global__ __launch_bounds__(256, 2) void rvq_argmax_tc(int q) {
    extern __shared__ float sm[];
    const uint32_t sb = smem_u32(sm);
    const int tid = threadIdx.x;
    const int lane = tid & 31, wid = tid >> 5;
    const int gid = lane >> 2, tg = lane & 3;
    const int wm = wid & 3, wn = wid >> 2;        // 4m x 2n, warp tile 32x64
    const int mtile = blockIdx.x >> 1, half = blockIdx.x & 1;
    const int row0 = mtile * 128;
    const __nv_bfloat16* __restrict__ cbh = g_cbh + ((size_t)q * BINS + half * 512) * DIM;

    for (int i = tid; i < 512; i += 256) sm[SQ(i)] = g_cbsq[q * BINS + half * 512 + i];

    // writer mapping: thread -> rows ur+{0,32,64,96}, 16B unit useg; phys unit = useg^(ur&7)
    const int ur = tid >> 3, useg = tid & 7;      // ur 0..31
    const char* aG = (const char*)g_resh + (size_t)(row0 + ur) * 512 + useg * 16;
    const char* bG = (const char*)cbh + (size_t)ur * 512 + useg * 16;
    const uint32_t wOff = (uint32_t)(ur * 128 + ((useg ^ (ur & 7)) << 4));

#define PREF(pg_) do { \
    const int slot_ = (pg_) % 3; \
    const uint32_t dA_ = sb + (uint32_t)(SA_OFF(slot_) * 4) + wOff; \
    const uint32_t dB_ = sb + (uint32_t)(SB_OFF(slot_) * 4) + wOff; \
    const char* sA_ = aG + ((pg_) & 3) * 128; \
    const char* sB_ = bG + (size_t)((pg_) >> 2) * 65536 + ((pg_) & 3) * 128; \
    cp_async16(dA_,           sA_); \
    cp_async16(dA_ + 4096u,   sA_ + 16384); \
    cp_async16(dA_ + 8192u,   sA_ + 32768); \
    cp_async16(dA_ + 12288u,  sA_ + 49152); \
    cp_async16(dB_,           sB_); \
    cp_async16(dB_ + 4096u,   sB_ + 16384); \
    cp_async16(dB_ + 8192u,   sB_ + 32768); \
    cp_async16(dB_ + 12288u,  sB_ + 49152); \
    CP_COMMIT(); \
} while (0)

#define LDS32(off_) (*(const uint32_t*)((const char*)sm + (off_)))

    float ts[4][2]; int ti[4][2];
    #pragma unroll
    for (int s = 0; s < 4; s++) {
        ts[s][0] = -FLT_MAX; ts[s][1] = -FLT_MAX;
        ti[s][0] = 0; ti[s][1] = 0;
    }

    float c[2][8][4];
    #pragma unroll
    for (int mi = 0; mi < 2; mi++)
        #pragma unroll
        for (int ni = 0; ni < 8; ni++)
            #pragma unroll
            for (int v = 0; v < 4; v++) c[mi][ni][v] = 0.0f;

#define FOLD(slot, sc, kg) do { \
    if ((sc) > ts[slot][0]) { \
        ts[slot][1] = ts[slot][0]; ti[slot][1] = ti[slot][0]; \
        ts[slot][0] = (sc); ti[slot][0] = (kg); \
    } else if ((sc) > ts[slot][1]) { ts[slot][1] = (sc); ti[slot][1] = (kg); } \
} while (0)

    PREF(0);
    PREF(1);

    #pragma unroll 1
    for (int g = 0; g < 16; g++) {
        CP_WAIT1();
        __syncthreads();
        if (g + 2 < 16) { PREF(g + 2); } else { CP_COMMIT(); }

        const int buf = g % 3;
        const uint32_t aB = (uint32_t)(SA_OFF(buf) * 4);
        const uint32_t bB = (uint32_t)(SB_OFF(buf) * 4);
        #pragma unroll
        for (int kk = 0; kk < 4; kk++) {
            // phys 16B unit = (2kk + {0,1}) ^ gid (row&7 == gid for all fragment rows)
            const uint32_t u0 = (uint32_t)(((2 * kk) ^ gid) << 4);
            const uint32_t u1 = u0 ^ 16u;
            uint32_t a[2][4];
            #pragma unroll
            for (int mi = 0; mi < 2; mi++) {
                uint32_t rb = aB + (uint32_t)((wm * 32 + mi * 16 + gid) * 128 + 4 * tg);
                a[mi][0] = LDS32(rb + u0);
                a[mi][2] = LDS32(rb + u1);
                a[mi][1] = LDS32(rb + 1024u + u0);
                a[mi][3] = LDS32(rb + 1024u + u1);
            }
            #pragma unroll
            for (int ni = 0; ni < 8; ni++) {
                uint32_t nb = bB + (uint32_t)((wn * 64 + ni * 8 + gid) * 128 + 4 * tg);
                uint32_t b[2] = { LDS32(nb + u0), LDS32(nb + u1) };
                mma_bf16(c[0][ni], a[0], b);
                mma_bf16(c[1][ni], a[1], b);
            }
        }

        if ((g & 3) == 3) {
            const int nt = g >> 2;
            #pragma unroll
            for (int mi = 0; mi < 2; mi++)
                #pragma unroll
                for (int ni = 0; ni < 8; ni++) {
                    int cc = wn * 64 + ni * 8 + tg * 2;
                    int kl = nt * 128 + cc;
                    int kg = half * 512 + kl;
                    float q0 = sm[SQ(kl)], q1 = sm[SQ(kl + 1)];
                    float s0 = 2.0f * c[mi][ni][0] - q0;
                    float s1 = 2.0f * c[mi][ni][1] - q1;
                    float s2 = 2.0f * c[mi][ni][2] - q0;
                    float s3 = 2.0f * c[mi][ni][3] - q1;
                    FOLD(mi * 2 + 0, s0, kg);
                    FOLD(mi * 2 + 0, s1, kg + 1);
                    FOLD(mi * 2 + 1, s2, kg);
                    FOLD(mi * 2 + 1, s3, kg + 1);
                    #pragma unroll
                    for (int v = 0; v < 4; v++) c[mi][ni][v] = 0.0f;
                }
            // stream out 2 candidates per (row, owner, nt); owner = wn*4+tg (8 owners)
            const int owner = wn * 4 + tg;
            #pragma unroll
            for (int s = 0; s < 4; s++) {
                int row = row0 + wm * 32 + (s >> 1) * 16 + (s & 1) * 8 + gid;
                size_t base = (size_t)row * 128 + half * 64 + nt * 16 + owner * 2;
                g_cand[base]     = ti[s][0];  g_cand_s[base]     = ts[s][0];
                g_cand[base + 1] = ti[s][1];  g_cand_s[base + 1] = ts[s][1];
                ts[s][0] = -FLT_MAX; ts[s][1] = -FLT_MAX;
                ti[s][0] = 0; ti[s][1] = 0;
            }
        }
    }
}

// ---------------- select + update: warp per row, ballot-compacted exact rescue ----------------
// bf16 score noise 3-sigma ~0.27; threshold 0.75 (2-sided margin). Unique survivor == winner.
__global__ __launch_bounds__(256) void rvq_select_update(const float* __restrict__ cbs,
                                                         float* __restrict__ codes_out, int q) {
    const int lane = threadIdx.x & 31;
    const int n = blockIdx.x * 8 + (threadIdx.x >> 5);   // warp per row
    const float* __restrict__ cb = cbs + (size_t)q * BINS * DIM;

    const size_t cbase = (size_t)n * 128;
    float s0 = g_cand_s[cbase + lane];
    float s1 = g_cand_s[cbase + 32 + lane];
    float s2 = g_cand_s[cbase + 64 + lane];
    float s3 = g_cand_s[cbase + 96 + lane];
    float mx = fmaxf(fmaxf(s0, s1), fmaxf(s2, s3));
    #pragma unroll
    for (int o = 16; o > 0; o >>= 1) mx = fmaxf(mx, __shfl_xor_sync(0xffffffffu, mx, o));

    const float thr = mx - 0.75f;
    unsigned m0 = __ballot_sync(0xffffffffu, s0 >= thr);
    unsigned m1 = __ballot_sync(0xffffffffu, s1 >= thr);
    unsigned m2 = __ballot_sync(0xffffffffu, s2 >= thr);
    unsigned m3 = __ballot_sync(0xffffffffu, s3 >= thr);

    int k;
    if (__popc(m0) + __popc(m1) + __popc(m2) + __popc(m3) == 1) {
        int ci = m0 ? (__ffs(m0) - 1)
               : m1 ? (31 + __ffs(m1))
               : m2 ? (63 + __ffs(m2))
               : (95 + __ffs(m3));
        k = g_cand[cbase + ci];
    } else {
        const float* r = g_res + (size_t)n * DIM;
        double best = -1e300; int bk = 1 << 30;
        unsigned masks[4] = { m0, m1, m2, m3 };
        #pragma unroll 1
        for (int j = 0; j < 4; j++) {
            unsigned mm = masks[j];
            while (mm) {
                int ci = 32 * j + __ffs(mm) - 1;
                mm &= mm - 1;
                int cand = g_cand[cbase + ci];
                const float* c = cb + (size_t)cand * DIM;
                double sc = 0.0;
                #pragma unroll
                for (int jj = 0; jj < 8; jj++) {
                    int pp = lane + jj * 32;
                    double rv = r[pp], cv = c[pp];
                    sc += cv * (2.0 * rv - cv);
                }
                #pragma unroll
                for (int o = 16; o > 0; o >>= 1)
                    sc += __shfl_xor_sync(0xffffffffu, sc, o);
                if (sc > best || (sc == best && cand < bk)) { best = sc; bk = cand; }
            }
        }
        k = bk;
    }

    // update: 8 elems per lane; write fp32 + bf16 residual, accumulate quantized
    const float* ck = cb + (size_t)k * DIM;
    float loss = 0.0f;
    #pragma unroll
    for (int j = 0; j < 8; j++) {
        int pp = lane + j * 32;
        float qv = ck[pp];
        size_t off = (size_t)n * DIM + pp;
        float rn = g_res[off] - qv;
        g_res[off] = rn;
        g_resh[off] = __float2bfloat16(rn);
        if (q == 0) g_acc[off] = qv;
        else        g_acc[off] += qv;
        loss += rn * rn;
    }
    #pragma unroll
    for (int o = 16; o > 0; o >>= 1) loss += __shfl_down_sync(0xffffffffu, loss, o);
    if (lane == 0) {
        g_partial[q * NN + n] = loss;
        codes_out[q * NN + n] = (float)k;
    }
}

// ---------------- finalize: g_acc (N,D natural) -> out (B,D,T) ----------------
__global__ void rvq_finalize(float* __restrict__ out) {
    __shared__ float s[32][33];
    int b = blockIdx.z, d0 = blockIdx.y * 32, t0 = blockIdx.x * 32;
    int tx = threadIdx.x, ty = threadIdx.y;
    int t = t0 + ty;
    if (t < TT) s[ty][tx] = g_acc[((size_t)(b * TT + t)) * DIM + d0 + tx];
    __syncthreads();
    int t2 = t0 + tx;
    if (t2 < TT) out[((size_t)b * DIM + d0 + ty) * TT + t2] = s[tx][ty];
}

// ---------------- penalty ----------------
__global__ void rvq_penalty(float* __restrict__ out) {
    __shared__ float red[8];
    const int tid = threadIdx.x;
    float s = 0.0f;
    for (int i = tid; i < NQ * NN; i += 256) s += g_partial[i];
    #pragma unroll
    for (int o = 16; o > 0; o >>= 1) s += __shfl_down_sync(0xffffffffu, s, o);
    if ((tid & 31) == 0) red[tid >> 5] = s;
    __syncthreads();
    if (tid == 0) {
        float tot = 0.0f;
        #pragma unroll
        for (int w = 0; w < 8; w++) tot += red[w];
        out[(size_t)BB * DIM * TT + (size_t)NQ * NN] =
            tot / ((float)NQ * (float)NN * (float)DIM);
    }
}

// ---------------- launch ----------------
extern "C" void kernel_launch(void* const* d_in, const int* in_sizes, int n_in,
                              void* d_out, int out_size) {
    const float* x   = (const float*)d_in[0];
    const float* cbs = (const float*)d_in[1];
    float* out = (float*)d_out;
    float* codes_out = out + (size_t)BB * DIM * TT;

    cudaFuncSetAttribute(rvq_argmax_tc,
                         cudaFuncAttributeMaxDynamicSharedMemorySize, SMEM_BYTES);

    dim3 tb(32, 32);
    rvq_init<<<dim3(47, 8, 17), tb>>>(x);
    rvq_cbsq<<<1024, 256>>>(cbs);
    rvq_cbh<<<(NQ * BINS * DIM + 255) / 256, 256>>>(cbs);

    for (int q = 0; q < NQ; q++) {
        rvq_argmax_tc<<<NTILE * 2, 256, SMEM_BYTES>>>(q);
        rvq_select_update<<<NN / 8, 256>>>(cbs, codes_out, q);
    }

    rvq_finalize<<<dim3(47, 8, 16), tb>>>(out);
    rvq_penalty<<<1, 256>>>(out);
}

// round 16
// speedup vs baseline: 2.6490x; 1.0927x over previous
#include <cuda_runtime.h>
#include <cuda_bf16.h>
#include <cstdint>
#include <float.h>

#define NQ    8
#define BINS  1024
#define DIM   256
#define BB    16
#define TT    1500
#define NN    (BB * TT)
#define NPAD  24064
#define NTILE 188

// device scratch (natural D order)
__device__ float          g_res[NPAD * DIM];
__device__ __nv_bfloat16  g_resh[NPAD * DIM];
__device__ float          g_acc[NPAD * DIM];
__device__ __nv_bfloat16  g_cbh[NQ * BINS * DIM];
__device__ int   g_cand[NPAD * 128];
__device__ float g_cand_s[NPAD * 128];
__device__ float g_cbsq[NQ * BINS];
__device__ float g_partial[NQ * NN];

// ---------------- helpers ----------------
__device__ __forceinline__ uint32_t smem_u32(const void* p) {
    uint32_t a;
    asm("{ .reg .u64 t; cvta.to.shared.u64 t, %1; cvt.u32.u64 %0, t; }" : "=r"(a) : "l"(p));
    return a;
}
__device__ __forceinline__ void cp_async16(uint32_t dst, const void* src) {
    asm volatile("cp.async.cg.shared.global [%0], [%1], 16;" :: "r"(dst), "l"(src) : "memory");
}
#define CP_COMMIT() asm volatile("cp.async.commit_group;" ::: "memory")
#define CP_WAIT1()  asm volatile("cp.async.wait_group 1;" ::: "memory")

__device__ __forceinline__ void mma_bf16(float* c, const uint32_t* a, const uint32_t* b) {
    asm volatile(
        "mma.sync.aligned.m16n8k16.row.col.f32.bf16.bf16.f32 "
        "{%0,%1,%2,%3}, {%4,%5,%6,%7}, {%8,%9}, {%0,%1,%2,%3};"
        : "+f"(c[0]), "+f"(c[1]), "+f"(c[2]), "+f"(c[3])
        : "r"(a[0]), "r"(a[1]), "r"(a[2]), "r"(a[3]), "r"(b[0]), "r"(b[1]));
}

// smem floats: A[3][128 rows x 32 words] @0, B[3][...] @12288, cbsq[256] @24576
// chunk = 128 rows/cols x K=64 bf16 (128B rows). Swizzle: phys 16B-unit = unit ^ (row & 7).
#define SA_OFF(s)   ((s) * 4096)
#define SB_OFF(s)   (12288 + (s) * 4096)
#define SQ(i)       (24576 + (i))
#define SMEM_BYTES  (24832 * 4)

// ---------------- init: x (B,D,T) -> g_res/g_resh (N,D natural); z==16 zeroes pad ----------------
__global__ void rvq_init(const float* __restrict__ x) {
    __shared__ float s[32][33];
    if (blockIdx.z == 16) {
        int idx = (blockIdx.y * 47 + blockIdx.x) * 1024 + threadIdx.y * 32 + threadIdx.x;
        if (idx < (NPAD - NN) * DIM) {
            g_res[(size_t)NN * DIM + idx] = 0.0f;
            g_resh[(size_t)NN * DIM + idx] = __float2bfloat16(0.0f);
        }
        return;
    }
    int b = blockIdx.z, d0 = blockIdx.y * 32, t0 = blockIdx.x * 32;
    int tx = threadIdx.x, ty = threadIdx.y;
    int t = t0 + tx;
    if (t < TT) s[ty][tx] = x[((size_t)b * DIM + d0 + ty) * TT + t];
    __syncthreads();
    int t2 = t0 + ty;
    if (t2 < TT) {
        float v = s[tx][ty];
        size_t off = ((size_t)(b * TT + t2)) * DIM + d0 + tx;
        g_res[off] = v;
        g_resh[off] = __float2bfloat16(v);
    }
}

// ---------------- cbsq + bf16 codebook copy ----------------
__global__ void rvq_cbsq(const float* __restrict__ cb) {
    int warp = (blockIdx.x * blockDim.x + threadIdx.x) >> 5;
    int lane = threadIdx.x & 31;
    if (warp >= NQ * BINS) return;
    const float* row = cb + (size_t)warp * DIM;
    float s = 0.0f;
    for (int d = lane; d < DIM; d += 32) { float c = row[d]; s += c * c; }
    #pragma unroll
    for (int o = 16; o > 0; o >>= 1) s += __shfl_down_sync(0xffffffffu, s, o);
    if (lane == 0) g_cbsq[warp] = s;
}

__global__ void rvq_cbh(const float* __restrict__ cbs) {
    size_t i = (size_t)blockIdx.x * blockDim.x + threadIdx.x;
    if (i >= (size_t)NQ * BINS * DIM) return;
    g_cbh[i] = __float2bfloat16(cbs[i]);
}

// ---------------- bf16 tensor-core argmax: 128 rows x 256 bins per CTA ----------------
// grid = 188 mtiles x 4 quarters = 752 CTAs; 256 threads, 8 warps (4m x 2n), warp tile 32x64.
// chunk g = nt*4 + kc, nt in {0,1} (128 bins each); 3-slot smem pipeline; 2 CTAs/SM.
// top-2 per (owner, nt): 8 owners * 2 * 2 nt * 4 quarters = 128 candidates/row (same as R15).
__global__ __launch_bounds__(256, 2) void rvq_argmax_tc(int q) {
    extern __shared__ float sm[];
    const uint32_t sb = smem_u32(sm);
    const int tid = threadIdx.x;
    const int lane = tid & 31, wid = tid >> 5;
    const int gid = lane >> 2, tg = lane & 3;
    const int wm = wid & 3, wn = wid >> 2;        // 4m x 2n, warp tile 32x64
    const int mtile = blockIdx.x >> 2, quarter = blockIdx.x & 3;
    const int row0 = mtile * 128;
    const __nv_bfloat16* __restrict__ cbh = g_cbh + ((size_t)q * BINS + quarter * 256) * DIM;

    sm[SQ(tid)] = g_cbsq[q * BINS + quarter * 256 + tid];

    // writer mapping: thread -> rows ur+{0,32,64,96}, 16B unit useg; phys unit = useg^(ur&7)
    const int ur = tid >> 3, useg = tid & 7;      // ur 0..31
    const char* aG = (const char*)g_resh + (size_t)(row0 + ur) * 512 + useg * 16;
    const char* bG = (const char*)cbh + (size_t)ur * 512 + useg * 16;
    const uint32_t wOff = (uint32_t)(ur * 128 + ((useg ^ (ur & 7)) << 4));

#define PREF(pg_) do { \
    const int slot_ = (pg_) % 3; \
    const uint32_t dA_ = sb + (uint32_t)(SA_OFF(slot_) * 4) + wOff; \
    const uint32_t dB_ = sb + (uint32_t)(SB_OFF(slot_) * 4) + wOff; \
    const char* sA_ = aG + ((pg_) & 3) * 128; \
    const char* sB_ = bG + (size_t)((pg_) >> 2) * 65536 + ((pg_) & 3) * 128; \
    cp_async16(dA_,           sA_); \
    cp_async16(dA_ + 4096u,   sA_ + 16384); \
    cp_async16(dA_ + 8192u,   sA_ + 32768); \
    cp_async16(dA_ + 12288u,  sA_ + 49152); \
    cp_async16(dB_,           sB_); \
    cp_async16(dB_ + 4096u,   sB_ + 16384); \
    cp_async16(dB_ + 8192u,   sB_ + 32768); \
    cp_async16(dB_ + 12288u,  sB_ + 49152); \
    CP_COMMIT(); \
} while (0)

#define LDS32(off_) (*(const uint32_t*)((const char*)sm + (off_)))

    float ts[4][2]; int ti[4][2];
    #pragma unroll
    for (int s = 0; s < 4; s++) {
        ts[s][0] = -FLT_MAX; ts[s][1] = -FLT_MAX;
        ti[s][0] = 0; ti[s][1] = 0;
    }

    float c[2][8][4];
    #pragma unroll
    for (int mi = 0; mi < 2; mi++)
        #pragma unroll
        for (int ni = 0; ni < 8; ni++)
            #pragma unroll
            for (int v = 0; v < 4; v++) c[mi][ni][v] = 0.0f;

#define FOLD(slot, sc, kg) do { \
    if ((sc) > ts[slot][0]) { \
        ts[slot][1] = ts[slot][0]; ti[slot][1] = ti[slot][0]; \
        ts[slot][0] = (sc); ti[slot][0] = (kg); \
    } else if ((sc) > ts[slot][1]) { ts[slot][1] = (sc); ti[slot][1] = (kg); } \
} while (0)

    PREF(0);
    PREF(1);

    #pragma unroll 1
    for (int g = 0; g < 8; g++) {
        CP_WAIT1();
        __syncthreads();
        if (g + 2 < 8) { PREF(g + 2); } else { CP_COMMIT(); }

        const int buf = g % 3;
        const uint32_t aB = (uint32_t)(SA_OFF(buf) * 4);
        const uint32_t bB = (uint32_t)(SB_OFF(buf) * 4);
        #pragma unroll
        for (int kk = 0; kk < 4; kk++) {
            const uint32_t u0 = (uint32_t)(((2 * kk) ^ gid) << 4);
            const uint32_t u1 = u0 ^ 16u;
            uint32_t a[2][4];
            #pragma unroll
            for (int mi = 0; mi < 2; mi++) {
                uint32_t rb = aB + (uint32_t)((wm * 32 + mi * 16 + gid) * 128 + 4 * tg);
                a[mi][0] = LDS32(rb + u0);
                a[mi][2] = LDS32(rb + u1);
                a[mi][1] = LDS32(rb + 1024u + u0);
                a[mi][3] = LDS32(rb + 1024u + u1);
            }
            #pragma unroll
            for (int ni = 0; ni < 8; ni++) {
                uint32_t nb = bB + (uint32_t)((wn * 64 + ni * 8 + gid) * 128 + 4 * tg);
                uint32_t b[2] = { LDS32(nb + u0), LDS32(nb + u1) };
                mma_bf16(c[0][ni], a[0], b);
                mma_bf16(c[1][ni], a[1], b);
            }
        }

        if ((g & 3) == 3) {
            const int nt = g >> 2;
            #pragma unroll
            for (int mi = 0; mi < 2; mi++)
                #pragma unroll
                for (int ni = 0; ni < 8; ni++) {
                    int cc = wn * 64 + ni * 8 + tg * 2;
                    int kl = nt * 128 + cc;
                    int kg = quarter * 256 + kl;
                    float q0 = sm[SQ(kl)], q1 = sm[SQ(kl + 1)];
                    float s0 = 2.0f * c[mi][ni][0] - q0;
                    float s1 = 2.0f * c[mi][ni][1] - q1;
                    float s2 = 2.0f * c[mi][ni][2] - q0;
                    float s3 = 2.0f * c[mi][ni][3] - q1;
                    FOLD(mi * 2 + 0, s0, kg);
                    FOLD(mi * 2 + 0, s1, kg + 1);
                    FOLD(mi * 2 + 1, s2, kg);
                    FOLD(mi * 2 + 1, s3, kg + 1);
                    #pragma unroll
                    for (int v = 0; v < 4; v++) c[mi][ni][v] = 0.0f;
                }
            // stream out 2 candidates per (row, owner, nt); owner = wn*4+tg (8 owners)
            const int owner = wn * 4 + tg;
            #pragma unroll
            for (int s = 0; s < 4; s++) {
                int row = row0 + wm * 32 + (s >> 1) * 16 + (s & 1) * 8 + gid;
                size_t base = (size_t)row * 128 + quarter * 32 + nt * 16 + owner * 2;
                g_cand[base]     = ti[s][0];  g_cand_s[base]     = ts[s][0];
                g_cand[base + 1] = ti[s][1];  g_cand_s[base + 1] = ts[s][1];
                ts[s][0] = -FLT_MAX; ts[s][1] = -FLT_MAX;
                ti[s][0] = 0; ti[s][1] = 0;
            }
        }
    }
}

// ---------------- select + update: warp per row, ballot-compacted exact rescue ----------------
// bf16 score noise 3-sigma ~0.27; threshold 0.75. Unique survivor == exact winner.
__global__ __launch_bounds__(256) void rvq_select_update(const float* __restrict__ cbs,
                                                         float* __restrict__ codes_out, int q) {
    const int lane = threadIdx.x & 31;
    const int n = blockIdx.x * 8 + (threadIdx.x >> 5);   // warp per row
    const float* __restrict__ cb = cbs + (size_t)q * BINS * DIM;

    const size_t cbase = (size_t)n * 128;
    float s0 = g_cand_s[cbase + lane];
    float s1 = g_cand_s[cbase + 32 + lane];
    float s2 = g_cand_s[cbase + 64 + lane];
    float s3 = g_cand_s[cbase + 96 + lane];
    float mx = fmaxf(fmaxf(s0, s1), fmaxf(s2, s3));
    #pragma unroll
    for (int o = 16; o > 0; o >>= 1) mx = fmaxf(mx, __shfl_xor_sync(0xffffffffu, mx, o));

    const float thr = mx - 0.75f;
    unsigned m0 = __ballot_sync(0xffffffffu, s0 >= thr);
    unsigned m1 = __ballot_sync(0xffffffffu, s1 >= thr);
    unsigned m2 = __ballot_sync(0xffffffffu, s2 >= thr);
    unsigned m3 = __ballot_sync(0xffffffffu, s3 >= thr);

    int k;
    if (__popc(m0) + __popc(m1) + __popc(m2) + __popc(m3) == 1) {
        int ci = m0 ? (__ffs(m0) - 1)
               : m1 ? (31 + __ffs(m1))
               : m2 ? (63 + __ffs(m2))
               : (95 + __ffs(m3));
        k = g_cand[cbase + ci];
    } else {
        const float* r = g_res + (size_t)n * DIM;
        double best = -1e300; int bk = 1 << 30;
        unsigned masks[4] = { m0, m1, m2, m3 };
        #pragma unroll 1
        for (int j = 0; j < 4; j++) {
            unsigned mm = masks[j];
            while (mm) {
                int ci = 32 * j + __ffs(mm) - 1;
                mm &= mm - 1;
                int cand = g_cand[cbase + ci];
                const float* c = cb + (size_t)cand * DIM;
                double sc = 0.0;
                #pragma unroll
                for (int jj = 0; jj < 8; jj++) {
                    int pp = lane + jj * 32;
                    double rv = r[pp], cv = c[pp];
                    sc += cv * (2.0 * rv - cv);
                }
                #pragma unroll
                for (int o = 16; o > 0; o >>= 1)
                    sc += __shfl_xor_sync(0xffffffffu, sc, o);
                if (sc > best || (sc == best && cand < bk)) { best = sc; bk = cand; }
            }
        }
        k = bk;
    }

    // update: 8 elems per lane; write fp32 + bf16 residual, accumulate quantized
    const float* ck = cb + (size_t)k * DIM;
    float loss = 0.0f;
    #pragma unroll
    for (int j = 0; j < 8; j++) {
        int pp = lane + j * 32;
        float qv = ck[pp];
        size_t off = (size_t)n * DIM + pp;
        float rn = g_res[off] - qv;
        g_res[off] = rn;
        g_resh[off] = __float2bfloat16(rn);
        if (q == 0) g_acc[off] = qv;
        else        g_acc[off] += qv;
        loss += rn * rn;
    }
    #pragma unroll
    for (int o = 16; o > 0; o >>= 1) loss += __shfl_down_sync(0xffffffffu, loss, o);
    if (lane == 0) {
        g_partial[q * NN + n] = loss;
        codes_out[q * NN + n] = (float)k;
    }
}

// ---------------- finalize: g_acc (N,D natural) -> out (B,D,T) ----------------
__global__ void rvq_finalize(float* __restrict__ out) {
    __shared__ float s[32][33];
    int b = blockIdx.z, d0 = blockIdx.y * 32, t0 = blockIdx.x * 32;
    int tx = threadIdx.x, ty = threadIdx.y;
    int t = t0 + ty;
    if (t < TT) s[ty][tx] = g_acc[((size_t)(b * TT + t)) * DIM + d0 + tx];
    __syncthreads();
    int t2 = t0 + tx;
    if (t2 < TT) out[((size_t)b * DIM + d0 + ty) * TT + t2] = s[tx][ty];
}

// ---------------- penalty ----------------
__global__ void rvq_penalty(float* __restrict__ out) {
    __shared__ float red[8];
    const int tid = threadIdx.x;
    float s = 0.0f;
    for (int i = tid; i < NQ * NN; i += 256) s += g_partial[i];
    #pragma unroll
    for (int o = 16; o > 0; o >>= 1) s += __shfl_down_sync(0xffffffffu, s, o);
    if ((tid & 31) == 0) red[tid >> 5] = s;
    __syncthreads();
    if (tid == 0) {
        float tot = 0.0f;
        #pragma unroll
        for (int w = 0; w < 8; w++) tot += red[w];
        out[(size_t)BB * DIM * TT + (size_t)NQ * NN] =
            tot / ((float)NQ * (float)NN * (float)DIM);
    }
}

// ---------------- launch ----------------
extern "C" void kernel_launch(void* const* d_in, const int* in_sizes, int n_in,
                              void* d_out, int out_size) {
    const float* x   = (const float*)d_in[0];
    const float* cbs = (const float*)d_in[1];
    float* out = (float*)d_out;
    float* codes_out = out + (size_t)BB * DIM * TT;

    cudaFuncSetAttribute(rvq_argmax_tc,
                         cudaFuncAttributeMaxDynamicSharedMemorySize, SMEM_BYTES);

    dim3 tb(32, 32);
    rvq_init<<<dim3(47, 8, 17), tb>>>(x);
    rvq_cbsq<<<1024, 256>>>(cbs);
    rvq_cbh<<<(NQ * BINS * DIM + 255) / 256, 256>>>(cbs);

    for (int q = 0; q < NQ; q++) {
        rvq_argmax_tc<<<NTILE * 4, 256, SMEM_BYTES>>>(q);
        rvq_select_update<<<NN / 8, 256>>>(cbs, codes_out, q);
    }

    rvq_finalize<<<dim3(47, 8, 16), tb>>>(out);
    rvq_penalty<<<1, 256>>>(out);
}

// round 17
// speedup vs baseline: 2.7026x; 1.0203x over previous
#include <cuda_runtime.h>
#include <cuda_bf16.h>
#include <cstdint>
#include <float.h>

#define NQ    8
#define BINS  1024
#define DIM   256
#define BB    16
#define TT    1500
#define NN    (BB * TT)
#define NPAD  24064
#define NTILE 188

// device scratch (natural D order)
__device__ float          g_res[NPAD * DIM];
__device__ __nv_bfloat16  g_resh[NPAD * DIM];
__device__ float          g_acc[NPAD * DIM];
__device__ __nv_bfloat16  g_cbh[NQ * BINS * DIM];
__device__ int   g_cand[NPAD * 128];
__device__ float g_cand_s[NPAD * 128];
__device__ float g_cbsq[NQ * BINS];
__device__ float g_partial[NQ * NN];

// ---------------- helpers ----------------
__device__ __forceinline__ uint32_t smem_u32(const void* p) {
    uint32_t a;
    asm("{ .reg .u64 t; cvta.to.shared.u64 t, %1; cvt.u32.u64 %0, t; }" : "=r"(a) : "l"(p));
    return a;
}
__device__ __forceinline__ void cp_async16(uint32_t dst, const void* src) {
    asm volatile("cp.async.cg.shared.global [%0], [%1], 16;" :: "r"(dst), "l"(src) : "memory");
}
#define CP_COMMIT() asm volatile("cp.async.commit_group;" ::: "memory")
#define CP_WAIT1()  asm volatile("cp.async.wait_group 1;" ::: "memory")

__device__ __forceinline__ void mma_bf16(float* c, const uint32_t* a, const uint32_t* b) {
    asm volatile(
        "mma.sync.aligned.m16n8k16.row.col.f32.bf16.bf16.f32 "
        "{%0,%1,%2,%3}, {%4,%5,%6,%7}, {%8,%9}, {%0,%1,%2,%3};"
        : "+f"(c[0]), "+f"(c[1]), "+f"(c[2]), "+f"(c[3])
        : "r"(a[0]), "r"(a[1]), "r"(a[2]), "r"(a[3]), "r"(b[0]), "r"(b[1]));
}

__device__ __forceinline__ void ldsm_x4(uint32_t* r, uint32_t addr) {
    asm volatile("ldmatrix.sync.aligned.m8n8.x4.shared.b16 {%0,%1,%2,%3}, [%4];"
                 : "=r"(r[0]), "=r"(r[1]), "=r"(r[2]), "=r"(r[3]) : "r"(addr));
}

// smem floats: A[3][128 rows x 32 words] @0, B[3][...] @12288, cbsq[256] @24576
// chunk = 128 rows/cols x K=64 bf16 (128B rows). Swizzle: phys 16B-unit = unit ^ (row & 7).
#define SA_OFF(s)   ((s) * 4096)
#define SB_OFF(s)   (12288 + (s) * 4096)
#define SQ(i)       (24576 + (i))
#define SMEM_BYTES  (24832 * 4)

// ---------------- init: x (B,D,T) -> g_res/g_resh (N,D natural); z==16 zeroes pad ----------------
__global__ void rvq_init(const float* __restrict__ x) {
    __shared__ float s[32][33];
    if (blockIdx.z == 16) {
        int idx = (blockIdx.y * 47 + blockIdx.x) * 1024 + threadIdx.y * 32 + threadIdx.x;
        if (idx < (NPAD - NN) * DIM) {
            g_res[(size_t)NN * DIM + idx] = 0.0f;
            g_resh[(size_t)NN * DIM + idx] = __float2bfloat16(0.0f);
        }
        return;
    }
    int b = blockIdx.z, d0 = blockIdx.y * 32, t0 = blockIdx.x * 32;
    int tx = threadIdx.x, ty = threadIdx.y;
    int t = t0 + tx;
    if (t < TT) s[ty][tx] = x[((size_t)b * DIM + d0 + ty) * TT + t];
    __syncthreads();
    int t2 = t0 + ty;
    if (t2 < TT) {
        float v = s[tx][ty];
        size_t off = ((size_t)(b * TT + t2)) * DIM + d0 + tx;
        g_res[off] = v;
        g_resh[off] = __float2bfloat16(v);
    }
}

// ---------------- cbsq + bf16 codebook copy ----------------
__global__ void rvq_cbsq(const float* __restrict__ cb) {
    int warp = (blockIdx.x * blockDim.x + threadIdx.x) >> 5;
    int lane = threadIdx.x & 31;
    if (warp >= NQ * BINS) return;
    const float* row = cb + (size_t)warp * DIM;
    float s = 0.0f;
    for (int d = lane; d < DIM; d += 32) { float c = row[d]; s += c * c; }
    #pragma unroll
    for (int o = 16; o > 0; o >>= 1) s += __shfl_down_sync(0xffffffffu, s, o);
    if (lane == 0) g_cbsq[warp] = s;
}

__global__ void rvq_cbh(const float* __restrict__ cbs) {
    size_t i = (size_t)blockIdx.x * blockDim.x + threadIdx.x;
    if (i >= (size_t)NQ * BINS * DIM) return;
    g_cbh[i] = __float2bfloat16(cbs[i]);
}

// ---------------- bf16 tensor-core argmax: 128 rows x 256 bins per CTA ----------------
// grid = 188 mtiles x 4 quarters = 752 CTAs; 256 threads, 8 warps (4m x 2n), warp tile 32x64.
// chunk g = nt*4 + kc, nt in {0,1} (128 bins each); 3-slot smem pipeline; 2 CTAs/SM.
// Fragments via ldmatrix.x4. top-2 per (owner, nt): 128 candidates/row total.
__global__ __launch_bounds__(256, 2) void rvq_argmax_tc(int q) {
    extern __shared__ float sm[];
    const uint32_t sb = smem_u32(sm);
    const int tid = threadIdx.x;
    const int lane = tid & 31, wid = tid >> 5;
    const int gid = lane >> 2, tg = lane & 3;
    const int wm = wid & 3, wn = wid >> 2;        // 4m x 2n, warp tile 32x64
    const int mtile = blockIdx.x >> 2, quarter = blockIdx.x & 3;
    const int row0 = mtile * 128;
    const __nv_bfloat16* __restrict__ cbh = g_cbh + ((size_t)q * BINS + quarter * 256) * DIM;

    sm[SQ(tid)] = g_cbsq[q * BINS + quarter * 256 + tid];

    // writer mapping: thread -> rows ur+{0,32,64,96}, 16B unit useg; phys unit = useg^(ur&7)
    const int ur = tid >> 3, useg = tid & 7;      // ur 0..31
    const char* aG = (const char*)g_resh + (size_t)(row0 + ur) * 512 + useg * 16;
    const char* bG = (const char*)cbh + (size_t)ur * 512 + useg * 16;
    const uint32_t wOff = (uint32_t)(ur * 128 + ((useg ^ (ur & 7)) << 4));

#define PREF(pg_) do { \
    const int slot_ = (pg_) % 3; \
    const uint32_t dA_ = sb + (uint32_t)(SA_OFF(slot_) * 4) + wOff; \
    const uint32_t dB_ = sb + (uint32_t)(SB_OFF(slot_) * 4) + wOff; \
    const char* sA_ = aG + ((pg_) & 3) * 128; \
    const char* sB_ = bG + (size_t)((pg_) >> 2) * 65536 + ((pg_) & 3) * 128; \
    cp_async16(dA_,           sA_); \
    cp_async16(dA_ + 4096u,   sA_ + 16384); \
    cp_async16(dA_ + 8192u,   sA_ + 32768); \
    cp_async16(dA_ + 12288u,  sA_ + 49152); \
    cp_async16(dB_,           sB_); \
    cp_async16(dB_ + 4096u,   sB_ + 16384); \
    cp_async16(dB_ + 8192u,   sB_ + 32768); \
    cp_async16(dB_ + 12288u,  sB_ + 49152); \
    CP_COMMIT(); \
} while (0)

    // ldmatrix per-lane address components (byte offsets within a chunk slot)
    // A: matrices (rows0-7,kh0)(rows8-15,kh0)(rows0-7,kh1)(rows8-15,kh1)
    const int aRow  = lane & 15;          // row within 16
    const int aHalf = lane >> 4;          // k-half
    // B: matrices (n0-7,kh0)(n0-7,kh1)(n8-15,kh0)(n8-15,kh1)
    const int bRow  = (lane & 7) | (((lane >> 4) & 1) << 3);
    const int bHalf = (lane >> 3) & 1;
    const int lx    = lane & 7;           // swizzle term (row&7 == lane&7 in both mappings)
    // row-base byte offsets (unit term added per kk)
    const uint32_t aRB0 = (uint32_t)((wm * 32 + aRow) * 128);        // mi=0
    const uint32_t aRB1 = aRB0 + 16u * 128u;                         // mi=1
    uint32_t bRB[4];
    #pragma unroll
    for (int p = 0; p < 4; p++) bRB[p] = (uint32_t)((wn * 64 + p * 16 + bRow) * 128);

    float ts[4][2]; int ti[4][2];
    #pragma unroll
    for (int s = 0; s < 4; s++) {
        ts[s][0] = -FLT_MAX; ts[s][1] = -FLT_MAX;
        ti[s][0] = 0; ti[s][1] = 0;
    }

    float c[2][8][4];
    #pragma unroll
    for (int mi = 0; mi < 2; mi++)
        #pragma unroll
        for (int ni = 0; ni < 8; ni++)
            #pragma unroll
            for (int v = 0; v < 4; v++) c[mi][ni][v] = 0.0f;

#define FOLD(slot, sc, kg) do { \
    if ((sc) > ts[slot][0]) { \
        ts[slot][1] = ts[slot][0]; ti[slot][1] = ti[slot][0]; \
        ts[slot][0] = (sc); ti[slot][0] = (kg); \
    } else if ((sc) > ts[slot][1]) { ts[slot][1] = (sc); ti[slot][1] = (kg); } \
} while (0)

    PREF(0);
    PREF(1);

    #pragma unroll 1
    for (int g = 0; g < 8; g++) {
        CP_WAIT1();
        __syncthreads();
        if (g + 2 < 8) { PREF(g + 2); } else { CP_COMMIT(); }

        const int buf = g % 3;
        const uint32_t aB = sb + (uint32_t)(SA_OFF(buf) * 4);
        const uint32_t bB = sb + (uint32_t)(SB_OFF(buf) * 4);
        #pragma unroll
        for (int kk = 0; kk < 4; kk++) {
            const uint32_t auo = (uint32_t)(((2 * kk + aHalf) ^ lx) << 4);
            const uint32_t buo = (uint32_t)(((2 * kk + bHalf) ^ lx) << 4);
            uint32_t a0[4], a1[4];
            ldsm_x4(a0, aB + aRB0 + auo);
            ldsm_x4(a1, aB + aRB1 + auo);
            #pragma unroll
            for (int p = 0; p < 4; p++) {
                uint32_t bb[4];
                ldsm_x4(bb, bB + bRB[p] + buo);
                mma_bf16(c[0][2 * p],     a0, bb);
                mma_bf16(c[1][2 * p],     a1, bb);
                mma_bf16(c[0][2 * p + 1], a0, bb + 2);
                mma_bf16(c[1][2 * p + 1], a1, bb + 2);
            }
        }

        if ((g & 3) == 3) {
            const int nt = g >> 2;
            #pragma unroll
            for (int mi = 0; mi < 2; mi++)
                #pragma unroll
                for (int ni = 0; ni < 8; ni++) {
                    int cc = wn * 64 + ni * 8 + tg * 2;
                    int kl = nt * 128 + cc;
                    int kg = quarter * 256 + kl;
                    float q0 = sm[SQ(kl)], q1 = sm[SQ(kl + 1)];
                    float s0 = 2.0f * c[mi][ni][0] - q0;
                    float s1 = 2.0f * c[mi][ni][1] - q1;
                    float s2 = 2.0f * c[mi][ni][2] - q0;
                    float s3 = 2.0f * c[mi][ni][3] - q1;
                    FOLD(mi * 2 + 0, s0, kg);
                    FOLD(mi * 2 + 0, s1, kg + 1);
                    FOLD(mi * 2 + 1, s2, kg);
                    FOLD(mi * 2 + 1, s3, kg + 1);
                    #pragma unroll
                    for (int v = 0; v < 4; v++) c[mi][ni][v] = 0.0f;
                }
            // stream out 2 candidates per (row, owner, nt); owner = wn*4+tg (8 owners)
            const int owner = wn * 4 + tg;
            #pragma unroll
            for (int s = 0; s < 4; s++) {
                int row = row0 + wm * 32 + (s >> 1) * 16 + (s & 1) * 8 + gid;
                size_t base = (size_t)row * 128 + quarter * 32 + nt * 16 + owner * 2;
                g_cand[base]     = ti[s][0];  g_cand_s[base]     = ts[s][0];
                g_cand[base + 1] = ti[s][1];  g_cand_s[base + 1] = ts[s][1];
                ts[s][0] = -FLT_MAX; ts[s][1] = -FLT_MAX;
                ti[s][0] = 0; ti[s][1] = 0;
            }
        }
    }
}

// ---------------- select + update: warp per row, ballot-compacted exact rescue ----------------
// bf16 score noise 3-sigma ~0.27; threshold 0.75. Unique survivor == exact winner.
__global__ __launch_bounds__(256) void rvq_select_update(const float* __restrict__ cbs,
                                                         float* __restrict__ codes_out, int q) {
    const int lane = threadIdx.x & 31;
    const int n = blockIdx.x * 8 + (threadIdx.x >> 5);   // warp per row
    const float* __restrict__ cb = cbs + (size_t)q * BINS * DIM;

    const size_t cbase = (size_t)n * 128;
    float s0 = g_cand_s[cbase + lane];
    float s1 = g_cand_s[cbase + 32 + lane];
    float s2 = g_cand_s[cbase + 64 + lane];
    float s3 = g_cand_s[cbase + 96 + lane];
    float mx = fmaxf(fmaxf(s0, s1), fmaxf(s2, s3));
    #pragma unroll
    for (int o = 16; o > 0; o >>= 1) mx = fmaxf(mx, __shfl_xor_sync(0xffffffffu, mx, o));

    const float thr = mx - 0.75f;
    unsigned m0 = __ballot_sync(0xffffffffu, s0 >= thr);
    unsigned m1 = __ballot_sync(0xffffffffu, s1 >= thr);
    unsigned m2 = __ballot_sync(0xffffffffu, s2 >= thr);
    unsigned m3 = __ballot_sync(0xffffffffu, s3 >= thr);

    int k;
    if (__popc(m0) + __popc(m1) + __popc(m2) + __popc(m3) == 1) {
        int ci = m0 ? (__ffs(m0) - 1)
               : m1 ? (31 + __ffs(m1))
               : m2 ? (63 + __ffs(m2))
               : (95 + __ffs(m3));
        k = g_cand[cbase + ci];
    } else {
        const float* r = g_res + (size_t)n * DIM;
        double best = -1e300; int bk = 1 << 30;
        unsigned masks[4] = { m0, m1, m2, m3 };
        #pragma unroll 1
        for (int j = 0; j < 4; j++) {
            unsigned mm = masks[j];
            while (mm) {
                int ci = 32 * j + __ffs(mm) - 1;
                mm &= mm - 1;
                int cand = g_cand[cbase + ci];
                const float* c = cb + (size_t)cand * DIM;
                double sc = 0.0;
                #pragma unroll
                for (int jj = 0; jj < 8; jj++) {
                    int pp = lane + jj * 32;
                    double rv = r[pp], cv = c[pp];
                    sc += cv * (2.0 * rv - cv);
                }
                #pragma unroll
                for (int o = 16; o > 0; o >>= 1)
                    sc += __shfl_xor_sync(0xffffffffu, sc, o);
                if (sc > best || (sc == best && cand < bk)) { best = sc; bk = cand; }
            }
        }
        k = bk;
    }

    // update: 8 elems per lane; write fp32 + bf16 residual, accumulate quantized
    const float* ck = cb + (size_t)k * DIM;
    float loss = 0.0f;
    #pragma unroll
    for (int j = 0; j < 8; j++) {
        int pp = lane + j * 32;
        float qv = ck[pp];
        size_t off = (size_t)n * DIM + pp;
        float rn = g_res[off] - qv;
        g_res[off] = rn;
        g_resh[off] = __float2bfloat16(rn);
        if (q == 0) g_acc[off] = qv;
        else        g_acc[off] += qv;
        loss += rn * rn;
    }
    #pragma unroll
    for (int o = 16; o > 0; o >>= 1) loss += __shfl_down_sync(0xffffffffu, loss, o);
    if (lane == 0) {
        g_partial[q * NN + n] = loss;
        codes_out[q * NN + n] = (float)k;
    }
}

// ---------------- finalize: g_acc (N,D natural) -> out (B,D,T) ----------------
__global__ void rvq_finalize(float* __restrict__ out) {
    __shared__ float s[32][33];
    int b = blockIdx.z, d0 = blockIdx.y * 32, t0 = blockIdx.x * 32;
    int tx = threadIdx.x, ty = threadIdx.y;
    int t = t0 + ty;
    if (t < TT) s[ty][tx] = g_acc[((size_t)(b * TT + t)) * DIM + d0 + tx];
    __syncthreads();
    int t2 = t0 + tx;
    if (t2 < TT) out[((size_t)b * DIM + d0 + ty) * TT + t2] = s[tx][ty];
}

// ---------------- penalty ----------------
__global__ void rvq_penalty(float* __restrict__ out) {
    __shared__ float red[8];
    const int tid = threadIdx.x;
    float s = 0.0f;
    for (int i = tid; i < NQ * NN; i += 256) s += g_partial[i];
    #pragma unroll
    for (int o = 16; o > 0; o >>= 1) s += __shfl_down_sync(0xffffffffu, s, o);
    if ((tid & 31) == 0) red[tid >> 5] = s;
    __syncthreads();
    if (tid == 0) {
        float tot = 0.0f;
        #pragma unroll
        for (int w = 0; w < 8; w++) tot += red[w];
        out[(size_t)BB * DIM * TT + (size_t)NQ * NN] =
            tot / ((float)NQ * (float)NN * (float)DIM);
    }
}

// ---------------- launch ----------------
extern "C" void kernel_launch(void* const* d_in, const int* in_sizes, int n_in,
                              void* d_out, int out_size) {
    const float* x   = (const float*)d_in[0];
    const float* cbs = (const float*)d_in[1];
    float* out = (float*)d_out;
    float* codes_out = out + (size_t)BB * DIM * TT;

    cudaFuncSetAttribute(rvq_argmax_tc,
                         cudaFuncAttributeMaxDynamicSharedMemorySize, SMEM_BYTES);

    dim3 tb(32, 32);
    rvq_init<<<dim3(47, 8, 17), tb>>>(x);
    rvq_cbsq<<<1024, 256>>>(cbs);
    rvq_cbh<<<(NQ * BINS * DIM + 255) / 256, 256>>>(cbs);

    for (int q = 0; q < NQ; q++) {
        rvq_argmax_tc<<<NTILE * 4, 256, SMEM_BYTES>>>(q);
        rvq_select_update<<<NN / 8, 256>>>(cbs, codes_out, q);
    }

    rvq_finalize<<<dim3(47, 8, 16), tb>>>(out);
    rvq_penalty<<<1, 256>>>(out);
}